// round 2
// baseline (speedup 1.0000x reference)
#include <cuda_runtime.h>
#include <cuda_bf16.h>
#include <math.h>

// ---------------- constants ----------------
#define B_   8
#define C_   768
#define H_   32
#define W_   32
#define T_   1024          // H*W
#define L_   2
#define FF_  3072
#define NPTS 2048          // PH*PW*K
#define TOPK_ 5
#define AROUND_ 5
#define NHEAD_ 8
#define HD_  96

// ---------------- scratch (device globals; allocation-free) ----------------
__device__ float g_pf    [(size_t)B_*NPTS*C_];
__device__ float g_hid   [(size_t)B_*NPTS*C_];
__device__ float g_coords[(size_t)B_*NPTS*2];
__device__ float g_score [(size_t)B_*NPTS];
__device__ int   g_topidx[B_*TOPK_];
__device__ float g_mem   [(size_t)B_*10*C_];
__device__ float g_tgt   [(size_t)B_*T_*C_];
__device__ float g_tmp   [(size_t)B_*T_*C_];
__device__ float g_qkv   [(size_t)B_*T_*3*C_];
__device__ float g_S     [(size_t)B_*NHEAD_*T_*T_];   // 256 MB
__device__ float g_attn  [(size_t)B_*T_*C_];
__device__ float g_ffh   [(size_t)B_*T_*FF_];
__device__ float g_memkv [(size_t)B_*10*2*C_];
__device__ float g_q     [(size_t)B_*T_*C_];

// ---------------- bilinear helpers (grid_sample, zeros pad, align_corners=False) --
__device__ __forceinline__ float bilin_img(const float* __restrict__ img, float ix, float iy){
    float x0f = floorf(ix), y0f = floorf(iy);
    int x0 = (int)x0f, y0 = (int)y0f;
    float wx1 = ix - x0f, wy1 = iy - y0f;
    float wx0 = 1.f - wx1, wy0 = 1.f - wy1;
    float v = 0.f;
    bool vx0 = (x0 >= 0) & (x0 < 32);
    bool vx1 = (x0 + 1 >= 0) & (x0 + 1 < 32);
    bool vy0 = (y0 >= 0) & (y0 < 32);
    bool vy1 = (y0 + 1 >= 0) & (y0 + 1 < 32);
    if (vx0 & vy0) v += img[y0*32 + x0]         * wx0 * wy0;
    if (vx1 & vy0) v += img[y0*32 + x0 + 1]     * wx1 * wy0;
    if (vx0 & vy1) v += img[(y0+1)*32 + x0]     * wx0 * wy1;
    if (vx1 & vy1) v += img[(y0+1)*32 + x0 + 1] * wx1 * wy1;
    return v;
}
__device__ __forceinline__ float bilin_pe(const float* __restrict__ pe, float ix, float iy, int c){
    float x0f = floorf(ix), y0f = floorf(iy);
    int x0 = (int)x0f, y0 = (int)y0f;
    float wx1 = ix - x0f, wy1 = iy - y0f;
    float wx0 = 1.f - wx1, wy0 = 1.f - wy1;
    float v = 0.f;
    bool vx0 = (x0 >= 0) & (x0 < 32);
    bool vx1 = (x0 + 1 >= 0) & (x0 + 1 < 32);
    bool vy0 = (y0 >= 0) & (y0 < 32);
    bool vy1 = (y0 + 1 >= 0) & (y0 + 1 < 32);
    if (vx0 & vy0) v += pe[((size_t)(y0*32 + x0))*C_ + c]         * wx0 * wy0;
    if (vx1 & vy0) v += pe[((size_t)(y0*32 + x0 + 1))*C_ + c]     * wx1 * wy0;
    if (vx0 & vy1) v += pe[((size_t)((y0+1)*32 + x0))*C_ + c]     * wx0 * wy1;
    if (vx1 & vy1) v += pe[((size_t)((y0+1)*32 + x0 + 1))*C_ + c] * wx1 * wy1;
    return v;
}

// ---------------- 1. blockwise sampling: coords + pf ----------------
__global__ void sample_kernel(const float* __restrict__ x, const float* __restrict__ brand,
                              float* __restrict__ pf, float* __restrict__ coords){
    int bn = blockIdx.x;                // b*2048 + n
    int b  = bn >> 11;
    int n  = bn & 2047;
    int k  = n & 1;
    int pw = (n >> 1) & 31;
    int ph = n >> 6;
    const float bs = 0.0625f;
    const float* br = brand + ((((size_t)b*32 + ph)*32 + pw)*2 + k)*2;
    float gx = br[0]*bs + (-1.0f + ph*bs);
    float gy = br[1]*bs + (-1.0f + pw*bs);
    float ix = ((gx + 1.0f)*32.0f - 1.0f)*0.5f;
    float iy = ((gy + 1.0f)*32.0f - 1.0f)*0.5f;
    if (threadIdx.x == 0){ coords[(size_t)bn*2] = gx; coords[(size_t)bn*2 + 1] = gy; }
    for (int c = threadIdx.x; c < C_; c += blockDim.x){
        const float* img = x + ((size_t)b*C_ + c)*T_;
        pf[(size_t)bn*C_ + c] = bilin_img(img, ix, iy);
    }
}

// ---------------- 2. generic SGEMM: C = A@B + bias (opt relu) ----------------
template<bool RELU>
__global__ __launch_bounds__(256)
void sgemm_kernel(const float* __restrict__ A, const float* __restrict__ B,
                  const float* __restrict__ bias, float* __restrict__ C,
                  int M, int N, int K, int lda, int ldb, int ldc){
    __shared__ float As[8][128];
    __shared__ float Bs[8][128];
    int tid = threadIdx.x;
    int row0 = blockIdx.y * 128;
    int col0 = blockIdx.x * 128;
    int tx = tid & 15, ty = tid >> 4;
    float acc[8][8];
    #pragma unroll
    for (int i = 0; i < 8; i++)
        #pragma unroll
        for (int j = 0; j < 8; j++) acc[i][j] = 0.f;

    int aRow = tid >> 1;
    int aCol = (tid & 1) * 4;
    int bRow = tid >> 5;
    int bCol = (tid & 31) * 4;

    for (int k0 = 0; k0 < K; k0 += 8){
        float4 av = make_float4(0.f,0.f,0.f,0.f);
        if (row0 + aRow < M)
            av = *(const float4*)(A + (size_t)(row0 + aRow)*lda + k0 + aCol);
        As[aCol+0][aRow] = av.x; As[aCol+1][aRow] = av.y;
        As[aCol+2][aRow] = av.z; As[aCol+3][aRow] = av.w;
        float4 bv = make_float4(0.f,0.f,0.f,0.f);
        if (col0 + bCol < N)
            bv = *(const float4*)(B + (size_t)(k0 + bRow)*ldb + col0 + bCol);
        *(float4*)&Bs[bRow][bCol] = bv;
        __syncthreads();
        #pragma unroll
        for (int kk = 0; kk < 8; kk++){
            float ar[8], br[8];
            #pragma unroll
            for (int i = 0; i < 8; i++) ar[i] = As[kk][ty*8 + i];
            #pragma unroll
            for (int j = 0; j < 8; j++) br[j] = Bs[kk][tx*8 + j];
            #pragma unroll
            for (int i = 0; i < 8; i++)
                #pragma unroll
                for (int j = 0; j < 8; j++)
                    acc[i][j] += ar[i] * br[j];
        }
        __syncthreads();
    }
    #pragma unroll
    for (int i = 0; i < 8; i++){
        int r = row0 + ty*8 + i;
        if (r >= M) continue;
        #pragma unroll
        for (int j = 0; j < 8; j += 4){
            int c = col0 + tx*8 + j;
            if (c >= N) continue;
            float4 o;
            o.x = acc[i][j+0] + (bias ? bias[c+0] : 0.f);
            o.y = acc[i][j+1] + (bias ? bias[c+1] : 0.f);
            o.z = acc[i][j+2] + (bias ? bias[c+2] : 0.f);
            o.w = acc[i][j+3] + (bias ? bias[c+3] : 0.f);
            if (RELU){
                o.x = fmaxf(o.x, 0.f); o.y = fmaxf(o.y, 0.f);
                o.z = fmaxf(o.z, 0.f); o.w = fmaxf(o.w, 0.f);
            }
            *(float4*)(C + (size_t)r*ldc + c) = o;
        }
    }
}

static void gemm(const float* A, const float* B, const float* bias, float* C,
                 int M, int N, int K, int lda, int ldb, int ldc, bool relu){
    dim3 grid((N + 127)/128, (M + 127)/128);
    if (relu) sgemm_kernel<true ><<<grid, 256>>>(A, B, bias, C, M, N, K, lda, ldb, ldc);
    else      sgemm_kernel<false><<<grid, 256>>>(A, B, bias, C, M, N, K, lda, ldb, ldc);
}

// ---------------- 3. score = hid . w2 + b2 ----------------
__global__ void score_kernel(const float* __restrict__ hid, const float* __restrict__ w2,
                             const float* __restrict__ b2, float* __restrict__ score){
    int row = blockIdx.x;
    float p = 0.f;
    for (int c = threadIdx.x; c < C_; c += 256) p += hid[(size_t)row*C_ + c] * w2[c];
    #pragma unroll
    for (int o = 16; o; o >>= 1) p += __shfl_down_sync(0xffffffffu, p, o);
    __shared__ float red[8];
    if ((threadIdx.x & 31) == 0) red[threadIdx.x >> 5] = p;
    __syncthreads();
    if (threadIdx.x == 0){
        float s = 0.f;
        #pragma unroll
        for (int i = 0; i < 8; i++) s += red[i];
        score[row] = s + b2[0];
    }
}

// ---------------- 4. top-5 per batch ----------------
__global__ void topk_kernel(const float* __restrict__ score, int* __restrict__ topidx){
    int b = blockIdx.x;
    __shared__ float sv[2048];
    __shared__ float rv[256];
    __shared__ int   ri[256];
    for (int j = threadIdx.x; j < 2048; j += 256) sv[j] = score[(size_t)b*2048 + j];
    __syncthreads();
    for (int t = 0; t < TOPK_; t++){
        float bv = -1e30f; int bi = 0x7fffffff;
        for (int j = threadIdx.x; j < 2048; j += 256){
            float v = sv[j];
            if (v > bv){ bv = v; bi = j; }
        }
        rv[threadIdx.x] = bv; ri[threadIdx.x] = bi;
        __syncthreads();
        for (int s = 128; s; s >>= 1){
            if (threadIdx.x < s){
                float v2 = rv[threadIdx.x + s]; int i2 = ri[threadIdx.x + s];
                if (v2 > rv[threadIdx.x] || (v2 == rv[threadIdx.x] && i2 < ri[threadIdx.x])){
                    rv[threadIdx.x] = v2; ri[threadIdx.x] = i2;
                }
            }
            __syncthreads();
        }
        if (threadIdx.x == 0){
            topidx[b*TOPK_ + t] = ri[0];
            sv[ri[0]] = -1e30f;
        }
        __syncthreads();
    }
}

// ---------------- 5. soft_align + modality query -> mem rows ----------------
__global__ void soft_align_kernel(const float* __restrict__ mainx, const float* __restrict__ pe,
                                  const float* __restrict__ arand, const float* __restrict__ mqrow,
                                  const float* __restrict__ pf, const float* __restrict__ coords,
                                  const int* __restrict__ topidx, float* __restrict__ memo, int rowBase){
    int b  = blockIdx.x / TOPK_;
    int nk = blockIdx.x % TOPK_;
    int idx = topidx[b*TOPK_ + nk];
    float px = coords[((size_t)b*NPTS + idx)*2 + 0];
    float py = coords[((size_t)b*NPTS + idx)*2 + 1];
    __shared__ float semb[AROUND_*C_];
    __shared__ float red[256];
    __shared__ float res[11];
    __shared__ float sw[AROUND_];
    float ixs[AROUND_], iys[AROUND_];
    #pragma unroll
    for (int a = 0; a < AROUND_; a++){
        const float* ar = arand + (((size_t)b*AROUND_ + a)*TOPK_ + nk)*2;
        float g0 = px + (ar[0]*2.f - 0.5f)*0.2f;
        float g1 = py + (ar[1]*2.f - 0.5f)*0.2f;
        g0 = fminf(fmaxf(g0, -1.f), 1.f);
        g1 = fminf(fmaxf(g1, -1.f), 1.f);
        ixs[a] = ((g0 + 1.f)*32.f - 1.f)*0.5f;
        iys[a] = ((g1 + 1.f)*32.f - 1.f)*0.5f;
    }
    const float* pfrow = pf + ((size_t)b*NPTS + idx)*C_;
    float rep2 = 0.f, num[AROUND_], af2[AROUND_];
    #pragma unroll
    for (int a = 0; a < AROUND_; a++){ num[a] = 0.f; af2[a] = 0.f; }
    for (int c = threadIdx.x; c < C_; c += 256){
        float r = pfrow[c];
        rep2 += r*r;
        const float* img = mainx + ((size_t)b*C_ + c)*T_;
        #pragma unroll
        for (int a = 0; a < AROUND_; a++){
            float af = bilin_img(img, ixs[a], iys[a]);
            num[a] += r*af;
            af2[a] += af*af;
            semb[a*C_ + c] = bilin_pe(pe, ixs[a], iys[a], c);
        }
    }
    float vals[11];
    vals[0] = rep2;
    #pragma unroll
    for (int a = 0; a < AROUND_; a++){ vals[1+a] = num[a]; vals[6+a] = af2[a]; }
    for (int v = 0; v < 11; v++){
        red[threadIdx.x] = vals[v];
        __syncthreads();
        for (int s = 128; s; s >>= 1){
            if (threadIdx.x < s) red[threadIdx.x] += red[threadIdx.x + s];
            __syncthreads();
        }
        if (threadIdx.x == 0) res[v] = red[0];
        __syncthreads();
    }
    if (threadIdx.x == 0){
        float rn = fmaxf(sqrtf(res[0]), 1e-8f);
        float s[AROUND_]; float mx = -1e30f;
        for (int a = 0; a < AROUND_; a++){
            s[a] = res[1+a] / (rn * fmaxf(sqrtf(res[6+a]), 1e-8f));
            mx = fmaxf(mx, s[a]);
        }
        float ss = 0.f;
        for (int a = 0; a < AROUND_; a++){ s[a] = expf(s[a] - mx); ss += s[a]; }
        for (int a = 0; a < AROUND_; a++) sw[a] = s[a] / ss;
    }
    __syncthreads();
    float w0 = sw[0], w1 = sw[1], w2 = sw[2], w3 = sw[3], w4 = sw[4];
    for (int c = threadIdx.x; c < C_; c += 256){
        float o = pfrow[c] + mqrow[c];
        o += semb[0*C_ + c]*w0 + semb[1*C_ + c]*w1 + semb[2*C_ + c]*w2
           + semb[3*C_ + c]*w3 + semb[4*C_ + c]*w4;
        memo[((size_t)b*10 + rowBase + nk)*C_ + c] = o;
    }
}

// ---------------- 6. tgt init (transpose + add pe/mq) ----------------
__global__ void tgt_init_kernel(const float* __restrict__ mainx, const float* __restrict__ mq,
                                const float* __restrict__ pe, float* __restrict__ tgt){
    __shared__ float tile[32][33];
    int c0 = blockIdx.x*32, t0 = blockIdx.y*32, b = blockIdx.z;
    for (int i = threadIdx.y; i < 32; i += 8)
        tile[i][threadIdx.x] = mainx[((size_t)b*C_ + c0 + i)*T_ + t0 + threadIdx.x];
    __syncthreads();
    for (int i = threadIdx.y; i < 32; i += 8){
        int t = t0 + i, c = c0 + threadIdx.x;
        tgt[((size_t)b*T_ + t)*C_ + c] = tile[threadIdx.x][i] + mq[c] + pe[(size_t)t*C_ + c];
    }
}

// ---------------- 7. attention scores S = scale * Q K^T ----------------
__global__ __launch_bounds__(256)
void attn_scores_kernel(const float* __restrict__ qkv, float* __restrict__ S){
    int bh = blockIdx.z, b = bh >> 3, h = bh & 7;
    int q0 = blockIdx.y * 64, k0 = blockIdx.x * 64;
    const float* qb = qkv + (size_t)b*T_*3*C_ + h*HD_;
    const float* kb = qb + C_;
    __shared__ float Qs[64][33];
    __shared__ float Ks[64][33];
    int tid = threadIdx.x, tx = tid & 15, ty = tid >> 4;
    float acc[4][4];
    #pragma unroll
    for (int i = 0; i < 4; i++)
        #pragma unroll
        for (int j = 0; j < 4; j++) acc[i][j] = 0.f;
    for (int kc = 0; kc < HD_; kc += 32){
        for (int idx = tid; idx < 2048; idx += 256){
            int r = idx >> 5, c = idx & 31;
            Qs[r][c] = qb[(size_t)(q0 + r)*(3*C_) + kc + c];
            Ks[r][c] = kb[(size_t)(k0 + r)*(3*C_) + kc + c];
        }
        __syncthreads();
        #pragma unroll
        for (int kk = 0; kk < 32; kk++){
            float a[4], bb[4];
            #pragma unroll
            for (int i = 0; i < 4; i++) a[i] = Qs[ty*4 + i][kk];
            #pragma unroll
            for (int j = 0; j < 4; j++) bb[j] = Ks[tx*4 + j][kk];
            #pragma unroll
            for (int i = 0; i < 4; i++)
                #pragma unroll
                for (int j = 0; j < 4; j++)
                    acc[i][j] += a[i]*bb[j];
        }
        __syncthreads();
    }
    const float scale = 0.10206207261596577f;  // 1/sqrt(96)
    float* Sp = S + ((size_t)bh*T_ + q0)*T_ + k0;
    #pragma unroll
    for (int i = 0; i < 4; i++){
        float4 o;
        o.x = acc[i][0]*scale; o.y = acc[i][1]*scale;
        o.z = acc[i][2]*scale; o.w = acc[i][3]*scale;
        *(float4*)&Sp[(size_t)(ty*4 + i)*T_ + tx*4] = o;
    }
}

// ---------------- 8. row softmax over 1024 ----------------
__global__ void softmax_kernel(float* __restrict__ S){
    size_t row = blockIdx.x;
    float* p = S + row*T_;
    int t = threadIdx.x;
    float v[4];
    float mx = -1e30f;
    #pragma unroll
    for (int i = 0; i < 4; i++){ v[i] = p[t + i*256]; mx = fmaxf(mx, v[i]); }
    __shared__ float red[256];
    red[t] = mx; __syncthreads();
    for (int s = 128; s; s >>= 1){
        if (t < s) red[t] = fmaxf(red[t], red[t + s]);
        __syncthreads();
    }
    mx = red[0]; __syncthreads();
    float sum = 0.f;
    #pragma unroll
    for (int i = 0; i < 4; i++){ v[i] = expf(v[i] - mx); sum += v[i]; }
    red[t] = sum; __syncthreads();
    for (int s = 128; s; s >>= 1){
        if (t < s) red[t] += red[t + s];
        __syncthreads();
    }
    float inv = 1.f / red[0];
    #pragma unroll
    for (int i = 0; i < 4; i++) p[t + i*256] = v[i]*inv;
}

// ---------------- 9. O = att @ V ----------------
__global__ __launch_bounds__(256)
void attn_av_kernel(const float* __restrict__ S, const float* __restrict__ qkv,
                    float* __restrict__ out){
    int bh = blockIdx.z, b = bh >> 3, h = bh & 7;
    int q0 = blockIdx.x * 64;
    __shared__ float Ss[64][65];
    __shared__ float Vs[64][96];
    int tid = threadIdx.x, tx = tid & 15, ty = tid >> 4;
    float acc[4][6];
    #pragma unroll
    for (int i = 0; i < 4; i++)
        #pragma unroll
        for (int j = 0; j < 6; j++) acc[i][j] = 0.f;
    const float* vb = qkv + (size_t)b*T_*3*C_ + 2*C_ + h*HD_;
    const float* Sp = S + ((size_t)bh*T_ + q0)*T_;
    for (int j0 = 0; j0 < T_; j0 += 64){
        for (int idx = tid; idx < 4096; idx += 256){
            int r = idx >> 6, c = idx & 63;
            Ss[r][c] = Sp[(size_t)r*T_ + j0 + c];
        }
        for (int idx = tid; idx < 6144; idx += 256){
            int r = idx / 96, c = idx % 96;
            Vs[r][c] = vb[(size_t)(j0 + r)*(3*C_) + c];
        }
        __syncthreads();
        #pragma unroll 16
        for (int jj = 0; jj < 64; jj++){
            float a[4], bb[6];
            #pragma unroll
            for (int i = 0; i < 4; i++) a[i] = Ss[ty*4 + i][jj];
            #pragma unroll
            for (int j = 0; j < 6; j++) bb[j] = Vs[jj][tx*6 + j];
            #pragma unroll
            for (int i = 0; i < 4; i++)
                #pragma unroll
                for (int j = 0; j < 6; j++)
                    acc[i][j] += a[i]*bb[j];
        }
        __syncthreads();
    }
    #pragma unroll
    for (int i = 0; i < 4; i++)
        #pragma unroll
        for (int j = 0; j < 6; j++)
            out[((size_t)b*T_ + q0 + ty*4 + i)*C_ + h*HD_ + tx*6 + j] = acc[i][j];
}

// ---------------- 10. cross-attention (10 keys) ----------------
__global__ void ca_attn_kernel(const float* __restrict__ q, const float* __restrict__ kv,
                               float* __restrict__ out){
    int bh = blockIdx.y, b = bh >> 3, h = bh & 7;
    int i = blockIdx.x*256 + threadIdx.x;
    __shared__ float Ks[10][96];
    __shared__ float Vsm[10][96];
    for (int idx = threadIdx.x; idx < 960; idx += 256){
        int j = idx / 96, d = idx % 96;
        Ks[j][d]  = kv[((size_t)b*10 + j)*(2*C_) + h*HD_ + d];
        Vsm[j][d] = kv[((size_t)b*10 + j)*(2*C_) + C_ + h*HD_ + d];
    }
    __syncthreads();
    const float* qr = q + ((size_t)b*T_ + i)*C_ + h*HD_;
    float s[10];
    #pragma unroll
    for (int j = 0; j < 10; j++) s[j] = 0.f;
    for (int d = 0; d < HD_; d++){
        float qd = qr[d];
        #pragma unroll
        for (int j = 0; j < 10; j++) s[j] += qd * Ks[j][d];
    }
    const float scale = 0.10206207261596577f;
    float mx = -1e30f;
    #pragma unroll
    for (int j = 0; j < 10; j++){ s[j] *= scale; mx = fmaxf(mx, s[j]); }
    float sum = 0.f;
    #pragma unroll
    for (int j = 0; j < 10; j++){ s[j] = expf(s[j] - mx); sum += s[j]; }
    float inv = 1.f / sum;
    #pragma unroll
    for (int j = 0; j < 10; j++) s[j] *= inv;
    float* orow = out + ((size_t)b*T_ + i)*C_ + h*HD_;
    for (int d = 0; d < HD_; d++){
        float o = 0.f;
        #pragma unroll
        for (int j = 0; j < 10; j++) o += s[j] * Vsm[j][d];
        orow[d] = o;
    }
}

// ---------------- 11. residual add + layernorm (in place on tgt) ----------------
__global__ void add_ln_kernel(float* __restrict__ tgt, const float* __restrict__ resid,
                              const float* __restrict__ w, const float* __restrict__ bb){
    int row = blockIdx.x, t = threadIdx.x;
    float* p = tgt + (size_t)row*C_;
    const float* r = resid + (size_t)row*C_;
    float v[3];
    float sum = 0.f;
    #pragma unroll
    for (int i = 0; i < 3; i++){ v[i] = p[t + i*256] + r[t + i*256]; sum += v[i]; }
    __shared__ float red[256];
    red[t] = sum; __syncthreads();
    for (int s = 128; s; s >>= 1){ if (t < s) red[t] += red[t + s]; __syncthreads(); }
    float m = red[0] * (1.f/768.f);
    __syncthreads();
    float s2 = 0.f;
    #pragma unroll
    for (int i = 0; i < 3; i++){ float d = v[i] - m; s2 += d*d; }
    red[t] = s2; __syncthreads();
    for (int s = 128; s; s >>= 1){ if (t < s) red[t] += red[t + s]; __syncthreads(); }
    float var = red[0] * (1.f/768.f);
    float rstd = rsqrtf(var + 1e-5f);
    #pragma unroll
    for (int i = 0; i < 3; i++){
        int c = t + i*256;
        p[c] = (v[i] - m)*rstd*w[c] + bb[c];
    }
}

// ---------------- 12. final transpose [B,T,C] -> [B,C,T] ----------------
__global__ void transpose_out_kernel(const float* __restrict__ tgt, float* __restrict__ out){
    __shared__ float tile[32][33];
    int c0 = blockIdx.x*32, t0 = blockIdx.y*32, b = blockIdx.z;
    for (int i = threadIdx.y; i < 32; i += 8)
        tile[i][threadIdx.x] = tgt[((size_t)b*T_ + t0 + i)*C_ + c0 + threadIdx.x];
    __syncthreads();
    for (int i = threadIdx.y; i < 32; i += 8)
        out[((size_t)b*C_ + c0 + i)*T_ + t0 + threadIdx.x] = tile[threadIdx.x][i];
}

// ---------------- launch ----------------
extern "C" void kernel_launch(void* const* d_in, const int* in_sizes, int n_in,
                              void* d_out, int out_size){
    const float* mainx      = (const float*)d_in[0];
    const float* others[2]  = {(const float*)d_in[1], (const float*)d_in[2]};
    const float* pe         = (const float*)d_in[3];
    const float* mq         = (const float*)d_in[4];
    const float* s_w1       = (const float*)d_in[5];
    const float* s_b1       = (const float*)d_in[6];
    const float* s_w2       = (const float*)d_in[7];
    const float* s_b2       = (const float*)d_in[8];
    const float* sa_in_w    = (const float*)d_in[9];
    const float* sa_in_b    = (const float*)d_in[10];
    const float* sa_out_w   = (const float*)d_in[11];
    const float* sa_out_b   = (const float*)d_in[12];
    const float* ca_in_w    = (const float*)d_in[13];
    const float* ca_in_b    = (const float*)d_in[14];
    const float* ca_out_w   = (const float*)d_in[15];
    const float* ca_out_b   = (const float*)d_in[16];
    const float* ff1_w      = (const float*)d_in[17];
    const float* ff1_b      = (const float*)d_in[18];
    const float* ff2_w      = (const float*)d_in[19];
    const float* ff2_b      = (const float*)d_in[20];
    const float* ln_w       = (const float*)d_in[21];
    const float* ln_b       = (const float*)d_in[22];
    const float* block_rand = (const float*)d_in[23];
    const float* around_rand= (const float*)d_in[24];
    float* out = (float*)d_out;

    float *pf, *hid, *coords, *score, *memb, *tgt, *tmp, *qkv, *Sb, *attn, *ffh, *memkv, *qb;
    int* topidx;
    cudaGetSymbolAddress((void**)&pf,     g_pf);
    cudaGetSymbolAddress((void**)&hid,    g_hid);
    cudaGetSymbolAddress((void**)&coords, g_coords);
    cudaGetSymbolAddress((void**)&score,  g_score);
    cudaGetSymbolAddress((void**)&topidx, g_topidx);
    cudaGetSymbolAddress((void**)&memb,   g_mem);
    cudaGetSymbolAddress((void**)&tgt,    g_tgt);
    cudaGetSymbolAddress((void**)&tmp,    g_tmp);
    cudaGetSymbolAddress((void**)&qkv,    g_qkv);
    cudaGetSymbolAddress((void**)&Sb,     g_S);
    cudaGetSymbolAddress((void**)&attn,   g_attn);
    cudaGetSymbolAddress((void**)&ffh,    g_ffh);
    cudaGetSymbolAddress((void**)&memkv,  g_memkv);
    cudaGetSymbolAddress((void**)&qb,     g_q);

    // ---- phase A: modalities ----
    for (int i = 0; i < 2; i++){
        sample_kernel<<<B_*NPTS, 256>>>(others[i], block_rand + (size_t)i*B_*32*32*2*2, pf, coords);
        gemm(pf, s_w1, s_b1, hid, B_*NPTS, C_, C_, C_, C_, C_, true);
        score_kernel<<<B_*NPTS, 256>>>(hid, s_w2, s_b2, score);
        topk_kernel<<<B_, 256>>>(score, topidx);
        soft_align_kernel<<<B_*TOPK_, 256>>>(mainx, pe,
                                             around_rand + (size_t)i*B_*AROUND_*TOPK_*2,
                                             mq + (size_t)(i+1)*C_,
                                             pf, coords, topidx, memb, i*TOPK_);
    }

    // ---- tgt init ----
    {
        dim3 g(C_/32, T_/32, B_); dim3 bl(32, 8);
        tgt_init_kernel<<<g, bl>>>(mainx, mq, pe, tgt);
    }

    // ---- decoder layers ----
    for (int l = 0; l < L_; l++){
        // self-attention
        gemm(tgt, sa_in_w + (size_t)l*C_*3*C_, sa_in_b + (size_t)l*3*C_, qkv,
             B_*T_, 3*C_, C_, C_, 3*C_, 3*C_, false);
        { dim3 g(16, 16, B_*NHEAD_); attn_scores_kernel<<<g, 256>>>(qkv, Sb); }
        softmax_kernel<<<B_*NHEAD_*T_, 256>>>(Sb);
        { dim3 g(16, 1, B_*NHEAD_); attn_av_kernel<<<g, 256>>>(Sb, qkv, attn); }
        gemm(attn, sa_out_w + (size_t)l*C_*C_, sa_out_b + (size_t)l*C_, tmp,
             B_*T_, C_, C_, C_, C_, C_, false);
        add_ln_kernel<<<B_*T_, 256>>>(tgt, tmp, ln_w + (size_t)(l*3+0)*C_, ln_b + (size_t)(l*3+0)*C_);

        // cross-attention
        gemm(tgt, ca_in_w + (size_t)l*C_*3*C_, ca_in_b + (size_t)l*3*C_, qb,
             B_*T_, C_, C_, C_, 3*C_, C_, false);
        gemm(memb, ca_in_w + (size_t)l*C_*3*C_ + C_, ca_in_b + (size_t)l*3*C_ + C_, memkv,
             B_*10, 2*C_, C_, C_, 3*C_, 2*C_, false);
        { dim3 g(T_/256, B_*NHEAD_); ca_attn_kernel<<<g, 256>>>(qb, memkv, attn); }
        gemm(attn, ca_out_w + (size_t)l*C_*C_, ca_out_b + (size_t)l*C_, tmp,
             B_*T_, C_, C_, C_, C_, C_, false);
        add_ln_kernel<<<B_*T_, 256>>>(tgt, tmp, ln_w + (size_t)(l*3+1)*C_, ln_b + (size_t)(l*3+1)*C_);

        // feed-forward
        gemm(tgt, ff1_w + (size_t)l*C_*FF_, ff1_b + (size_t)l*FF_, ffh,
             B_*T_, FF_, C_, C_, FF_, FF_, true);
        gemm(ffh, ff2_w + (size_t)l*FF_*C_, ff2_b + (size_t)l*C_, tmp,
             B_*T_, C_, FF_, FF_, C_, C_, false);
        add_ln_kernel<<<B_*T_, 256>>>(tgt, tmp, ln_w + (size_t)(l*3+2)*C_, ln_b + (size_t)(l*3+2)*C_);
    }

    // ---- output transpose ----
    {
        dim3 g(C_/32, T_/32, B_); dim3 bl(32, 8);
        transpose_out_kernel<<<g, bl>>>(tgt, out);
    }
}

// round 3
// speedup vs baseline: 2.2802x; 2.2802x over previous
#include <cuda_runtime.h>
#include <cuda_bf16.h>
#include <math.h>
#include <stdint.h>

// ---------------- constants ----------------
#define B_   8
#define C_   768
#define H_   32
#define W_   32
#define T_   1024          // H*W
#define L_   2
#define FF_  3072
#define NPTS 2048          // PH*PW*K
#define TOPK_ 5
#define AROUND_ 5
#define NHEAD_ 8
#define HD_  96

// ---------------- scratch (device globals; allocation-free) ----------------
__device__ float g_pf    [(size_t)B_*NPTS*C_];
__device__ float g_hid   [(size_t)B_*NPTS*C_];
__device__ float g_coords[(size_t)B_*NPTS*2];
__device__ float g_score [(size_t)B_*NPTS];
__device__ int   g_topidx[B_*TOPK_];
__device__ float g_mem   [(size_t)B_*10*C_];
__device__ float g_tgt   [(size_t)B_*T_*C_];
__device__ float g_tmp   [(size_t)B_*T_*C_];
__device__ float g_qkv   [(size_t)B_*T_*3*C_];
__device__ float g_S     [(size_t)B_*NHEAD_*T_*T_];   // 256 MB
__device__ float g_attn  [(size_t)B_*T_*C_];
__device__ float g_ffh   [(size_t)B_*T_*FF_];
__device__ float g_memkv [(size_t)B_*10*2*C_];
__device__ float g_q     [(size_t)B_*T_*C_];

// ---------------- tf32 helpers ----------------
__device__ __forceinline__ float f2tf32(float x){
    uint32_t u; asm("cvt.rna.tf32.f32 %0, %1;" : "=r"(u) : "f"(x));
    return __uint_as_float(u);
}
__device__ __forceinline__ void mma8(float* d, const float* a, const float* b){
    asm volatile("mma.sync.aligned.m16n8k8.row.col.f32.tf32.tf32.f32 "
        "{%0,%1,%2,%3},{%4,%5,%6,%7},{%8,%9},{%0,%1,%2,%3};\n"
        : "+f"(d[0]), "+f"(d[1]), "+f"(d[2]), "+f"(d[3])
        : "r"(__float_as_uint(a[0])), "r"(__float_as_uint(a[1])),
          "r"(__float_as_uint(a[2])), "r"(__float_as_uint(a[3])),
          "r"(__float_as_uint(b[0])), "r"(__float_as_uint(b[1])));
}

// ---------------- TF32 MMA GEMM ----------------
// C[m][n] = scale * sum_k A[m][k] * (NT ? B[n][k] : B[k][n]) + bias[n], opt relu.
// Batched over blockIdx.z with (z>>3, z&7) stride pairs for odd batch layouts.
// Block tile 128x128, 8 warps (2x4), warp tile 64x32, k-step 16.
// EXACT: 3xTF32 compensated (hi*hi + hi*lo + lo*hi), single-buffered smem.
template<bool NT, bool EXACT, bool RELU>
__global__ __launch_bounds__(256)
void mma_gemm_kernel(const float* __restrict__ A, const float* __restrict__ B,
                     const float* __restrict__ bias, float* __restrict__ C,
                     int M, int N, int K, int lda, int ldb, int ldc,
                     long sA1, long sA2, long sB1, long sB2, long sC1, long sC2,
                     float scale)
{
    const int PAD = 136;                       // bank stride 8 -> conflict-free frags
    const int SEG = (EXACT ? 4 : 2) * 16 * PAD;
    __shared__ float smem[(EXACT ? 1 : 2) * ((EXACT ? 4 : 2) * 16 * PAD)];

    int z = blockIdx.z, zb = z >> 3, zh = z & 7;
    A += (size_t)zb * sA1 + (size_t)zh * sA2;
    B += (size_t)zb * sB1 + (size_t)zh * sB2;
    C += (size_t)zb * sC1 + (size_t)zh * sC2;

    int tid = threadIdx.x, lane = tid & 31, warp = tid >> 5;
    int gid = lane >> 2, tig = lane & 3;
    int wm = warp >> 2, wn = warp & 3;
    int row0 = blockIdx.y * 128, col0 = blockIdx.x * 128;

    float acc[4][4][4];
    #pragma unroll
    for (int i = 0; i < 4; i++)
        #pragma unroll
        for (int j = 0; j < 4; j++)
            #pragma unroll
            for (int r = 0; r < 4; r++) acc[i][j][r] = 0.f;

    float4 ra[2], rb[2];
    const float4 zero4 = make_float4(0.f,0.f,0.f,0.f);

    auto gload = [&](int k0){
        #pragma unroll
        for (int i = 0; i < 2; i++){
            int idx = tid + 256*i;
            int arow = idx >> 2, ac4 = idx & 3;
            int gr = row0 + arow;
            ra[i] = (gr < M) ? *(const float4*)(A + (size_t)gr*lda + k0 + ac4*4) : zero4;
            if (NT){
                int bn = idx >> 2, bc4 = idx & 3;
                int gn = col0 + bn;
                rb[i] = (gn < N) ? *(const float4*)(B + (size_t)gn*ldb + k0 + bc4*4) : zero4;
            } else {
                int brow = idx >> 5, bc4 = idx & 31;
                int gc = col0 + bc4*4;
                rb[i] = (gc < N) ? *(const float4*)(B + (size_t)(k0 + brow)*ldb + gc) : zero4;
            }
        }
    };

    auto sstore = [&](int buf){
        float* Ahi = smem + buf*SEG;
        float* Bhi = Ahi + 16*PAD;
        float* Alo = Ahi + 2*16*PAD;
        float* Blo = Ahi + 3*16*PAD;
        #pragma unroll
        for (int i = 0; i < 2; i++){
            int idx = tid + 256*i;
            int arow = idx >> 2, ac4 = idx & 3;
            const float* pa = (const float*)&ra[i];
            #pragma unroll
            for (int j = 0; j < 4; j++){
                float v = pa[j], h = f2tf32(v);
                Ahi[(ac4*4 + j)*PAD + arow] = h;
                if (EXACT) Alo[(ac4*4 + j)*PAD + arow] = f2tf32(v - h);
            }
            const float* pb = (const float*)&rb[i];
            if (NT){
                int bn = idx >> 2, bc4 = idx & 3;
                #pragma unroll
                for (int j = 0; j < 4; j++){
                    float v = pb[j], h = f2tf32(v);
                    Bhi[(bc4*4 + j)*PAD + bn] = h;
                    if (EXACT) Blo[(bc4*4 + j)*PAD + bn] = f2tf32(v - h);
                }
            } else {
                int brow = idx >> 5, bc4 = idx & 31;
                float4 h4, l4;
                h4.x = f2tf32(pb[0]); h4.y = f2tf32(pb[1]);
                h4.z = f2tf32(pb[2]); h4.w = f2tf32(pb[3]);
                *(float4*)&Bhi[brow*PAD + bc4*4] = h4;
                if (EXACT){
                    l4.x = f2tf32(pb[0]-h4.x); l4.y = f2tf32(pb[1]-h4.y);
                    l4.z = f2tf32(pb[2]-h4.z); l4.w = f2tf32(pb[3]-h4.w);
                    *(float4*)&Blo[brow*PAD + bc4*4] = l4;
                }
            }
        }
    };

    auto compute = [&](int buf){
        const float* Ahi = smem + buf*SEG;
        const float* Bhi = Ahi + 16*PAD;
        const float* Alo = Ahi + 2*16*PAD;
        const float* Blo = Ahi + 3*16*PAD;
        #pragma unroll
        for (int kk = 0; kk < 16; kk += 8){
            int k1 = (kk + tig)*PAD, k2 = (kk + tig + 4)*PAD;
            float ah[4][4], bh[4][2], al[4][4], bl[4][2];
            #pragma unroll
            for (int ma = 0; ma < 4; ma++){
                int m = wm*64 + ma*16 + gid;
                ah[ma][0] = Ahi[k1 + m];     ah[ma][1] = Ahi[k1 + m + 8];
                ah[ma][2] = Ahi[k2 + m];     ah[ma][3] = Ahi[k2 + m + 8];
                if (EXACT){
                    al[ma][0] = Alo[k1 + m]; al[ma][1] = Alo[k1 + m + 8];
                    al[ma][2] = Alo[k2 + m]; al[ma][3] = Alo[k2 + m + 8];
                }
            }
            #pragma unroll
            for (int na = 0; na < 4; na++){
                int n = wn*32 + na*8 + gid;
                bh[na][0] = Bhi[k1 + n]; bh[na][1] = Bhi[k2 + n];
                if (EXACT){ bl[na][0] = Blo[k1 + n]; bl[na][1] = Blo[k2 + n]; }
            }
            #pragma unroll
            for (int ma = 0; ma < 4; ma++)
                #pragma unroll
                for (int na = 0; na < 4; na++){
                    mma8(acc[ma][na], ah[ma], bh[na]);
                    if (EXACT){
                        mma8(acc[ma][na], ah[ma], bl[na]);
                        mma8(acc[ma][na], al[ma], bh[na]);
                    }
                }
        }
    };

    int nk = K / 16;
    if (EXACT){
        for (int it = 0; it < nk; it++){
            if (it == 0) gload(0);
            if (it > 0) __syncthreads();
            sstore(0);
            __syncthreads();
            if (it + 1 < nk) gload((it + 1)*16);
            compute(0);
        }
    } else {
        gload(0); sstore(0); __syncthreads();
        for (int it = 0; it < nk; it++){
            if (it + 1 < nk) gload((it + 1)*16);
            compute(it & 1);
            if (it + 1 < nk){ __syncthreads(); sstore((it + 1)&1); __syncthreads(); }
        }
    }

    // epilogue
    #pragma unroll
    for (int ma = 0; ma < 4; ma++){
        int r0 = row0 + wm*64 + ma*16 + gid;
        #pragma unroll
        for (int na = 0; na < 4; na++){
            int c = col0 + wn*32 + na*8 + 2*tig;
            if (c >= N) continue;
            float b0 = bias ? bias[c] : 0.f;
            float b1 = bias ? bias[c+1] : 0.f;
            float x0 = acc[ma][na][0]*scale + b0;
            float x1 = acc[ma][na][1]*scale + b1;
            float x2 = acc[ma][na][2]*scale + b0;
            float x3 = acc[ma][na][3]*scale + b1;
            if (RELU){
                x0 = fmaxf(x0, 0.f); x1 = fmaxf(x1, 0.f);
                x2 = fmaxf(x2, 0.f); x3 = fmaxf(x3, 0.f);
            }
            if (r0 < M){ float2 o = make_float2(x0, x1); *(float2*)&C[(size_t)r0*ldc + c] = o; }
            if (r0 + 8 < M){ float2 o = make_float2(x2, x3); *(float2*)&C[(size_t)(r0+8)*ldc + c] = o; }
        }
    }
}

static void mma_gemm(const float* A, const float* B, const float* bias, float* C,
                     int M, int N, int K, int lda, int ldb, int ldc, int gz,
                     long sA1, long sA2, long sB1, long sB2, long sC1, long sC2,
                     float scale, bool nt, bool exact, bool relu){
    dim3 grid((N + 127)/128, (M + 127)/128, gz);
    if (nt)
        mma_gemm_kernel<true,false,false><<<grid,256>>>(A,B,bias,C,M,N,K,lda,ldb,ldc,sA1,sA2,sB1,sB2,sC1,sC2,scale);
    else if (exact)
        mma_gemm_kernel<false,true,true><<<grid,256>>>(A,B,bias,C,M,N,K,lda,ldb,ldc,sA1,sA2,sB1,sB2,sC1,sC2,scale);
    else if (relu)
        mma_gemm_kernel<false,false,true><<<grid,256>>>(A,B,bias,C,M,N,K,lda,ldb,ldc,sA1,sA2,sB1,sB2,sC1,sC2,scale);
    else
        mma_gemm_kernel<false,false,false><<<grid,256>>>(A,B,bias,C,M,N,K,lda,ldb,ldc,sA1,sA2,sB1,sB2,sC1,sC2,scale);
}

// ---------------- bilinear helpers ----------------
__device__ __forceinline__ float bilin_img(const float* __restrict__ img, float ix, float iy){
    float x0f = floorf(ix), y0f = floorf(iy);
    int x0 = (int)x0f, y0 = (int)y0f;
    float wx1 = ix - x0f, wy1 = iy - y0f;
    float wx0 = 1.f - wx1, wy0 = 1.f - wy1;
    float v = 0.f;
    bool vx0 = (x0 >= 0) & (x0 < 32);
    bool vx1 = (x0 + 1 >= 0) & (x0 + 1 < 32);
    bool vy0 = (y0 >= 0) & (y0 < 32);
    bool vy1 = (y0 + 1 >= 0) & (y0 + 1 < 32);
    if (vx0 & vy0) v += img[y0*32 + x0]         * wx0 * wy0;
    if (vx1 & vy0) v += img[y0*32 + x0 + 1]     * wx1 * wy0;
    if (vx0 & vy1) v += img[(y0+1)*32 + x0]     * wx0 * wy1;
    if (vx1 & vy1) v += img[(y0+1)*32 + x0 + 1] * wx1 * wy1;
    return v;
}
__device__ __forceinline__ float bilin_pe(const float* __restrict__ pe, float ix, float iy, int c){
    float x0f = floorf(ix), y0f = floorf(iy);
    int x0 = (int)x0f, y0 = (int)y0f;
    float wx1 = ix - x0f, wy1 = iy - y0f;
    float wx0 = 1.f - wx1, wy0 = 1.f - wy1;
    float v = 0.f;
    bool vx0 = (x0 >= 0) & (x0 < 32);
    bool vx1 = (x0 + 1 >= 0) & (x0 + 1 < 32);
    bool vy0 = (y0 >= 0) & (y0 < 32);
    bool vy1 = (y0 + 1 >= 0) & (y0 + 1 < 32);
    if (vx0 & vy0) v += pe[((size_t)(y0*32 + x0))*C_ + c]         * wx0 * wy0;
    if (vx1 & vy0) v += pe[((size_t)(y0*32 + x0 + 1))*C_ + c]     * wx1 * wy0;
    if (vx0 & vy1) v += pe[((size_t)((y0+1)*32 + x0))*C_ + c]     * wx0 * wy1;
    if (vx1 & vy1) v += pe[((size_t)((y0+1)*32 + x0 + 1))*C_ + c] * wx1 * wy1;
    return v;
}

// ---------------- blockwise sampling ----------------
__global__ void sample_kernel(const float* __restrict__ x, const float* __restrict__ brand,
                              float* __restrict__ pf, float* __restrict__ coords){
    int bn = blockIdx.x;
    int b  = bn >> 11;
    int n  = bn & 2047;
    int k  = n & 1;
    int pw = (n >> 1) & 31;
    int ph = n >> 6;
    const float bs = 0.0625f;
    const float* br = brand + ((((size_t)b*32 + ph)*32 + pw)*2 + k)*2;
    float gx = br[0]*bs + (-1.0f + ph*bs);
    float gy = br[1]*bs + (-1.0f + pw*bs);
    float ix = ((gx + 1.0f)*32.0f - 1.0f)*0.5f;
    float iy = ((gy + 1.0f)*32.0f - 1.0f)*0.5f;
    if (threadIdx.x == 0){ coords[(size_t)bn*2] = gx; coords[(size_t)bn*2 + 1] = gy; }
    for (int c = threadIdx.x; c < C_; c += blockDim.x){
        const float* img = x + ((size_t)b*C_ + c)*T_;
        pf[(size_t)bn*C_ + c] = bilin_img(img, ix, iy);
    }
}

// ---------------- score dot ----------------
__global__ void score_kernel(const float* __restrict__ hid, const float* __restrict__ w2,
                             const float* __restrict__ b2, float* __restrict__ score){
    int row = blockIdx.x;
    float p = 0.f;
    for (int c = threadIdx.x; c < C_; c += 256) p += hid[(size_t)row*C_ + c] * w2[c];
    #pragma unroll
    for (int o = 16; o; o >>= 1) p += __shfl_down_sync(0xffffffffu, p, o);
    __shared__ float red[8];
    if ((threadIdx.x & 31) == 0) red[threadIdx.x >> 5] = p;
    __syncthreads();
    if (threadIdx.x == 0){
        float s = 0.f;
        #pragma unroll
        for (int i = 0; i < 8; i++) s += red[i];
        score[row] = s + b2[0];
    }
}

// ---------------- top-5 ----------------
__global__ void topk_kernel(const float* __restrict__ score, int* __restrict__ topidx){
    int b = blockIdx.x;
    __shared__ float sv[2048];
    __shared__ float rv[256];
    __shared__ int   ri[256];
    for (int j = threadIdx.x; j < 2048; j += 256) sv[j] = score[(size_t)b*2048 + j];
    __syncthreads();
    for (int t = 0; t < TOPK_; t++){
        float bv = -1e30f; int bi = 0x7fffffff;
        for (int j = threadIdx.x; j < 2048; j += 256){
            float v = sv[j];
            if (v > bv){ bv = v; bi = j; }
        }
        rv[threadIdx.x] = bv; ri[threadIdx.x] = bi;
        __syncthreads();
        for (int s = 128; s; s >>= 1){
            if (threadIdx.x < s){
                float v2 = rv[threadIdx.x + s]; int i2 = ri[threadIdx.x + s];
                if (v2 > rv[threadIdx.x] || (v2 == rv[threadIdx.x] && i2 < ri[threadIdx.x])){
                    rv[threadIdx.x] = v2; ri[threadIdx.x] = i2;
                }
            }
            __syncthreads();
        }
        if (threadIdx.x == 0){
            topidx[b*TOPK_ + t] = ri[0];
            sv[ri[0]] = -1e30f;
        }
        __syncthreads();
    }
}

// ---------------- soft_align ----------------
__global__ void soft_align_kernel(const float* __restrict__ mainx, const float* __restrict__ pe,
                                  const float* __restrict__ arand, const float* __restrict__ mqrow,
                                  const float* __restrict__ pf, const float* __restrict__ coords,
                                  const int* __restrict__ topidx, float* __restrict__ memo, int rowBase){
    int b  = blockIdx.x / TOPK_;
    int nk = blockIdx.x % TOPK_;
    int idx = topidx[b*TOPK_ + nk];
    float px = coords[((size_t)b*NPTS + idx)*2 + 0];
    float py = coords[((size_t)b*NPTS + idx)*2 + 1];
    __shared__ float semb[AROUND_*C_];
    __shared__ float red[256];
    __shared__ float res[11];
    __shared__ float sw[AROUND_];
    float ixs[AROUND_], iys[AROUND_];
    #pragma unroll
    for (int a = 0; a < AROUND_; a++){
        const float* ar = arand + (((size_t)b*AROUND_ + a)*TOPK_ + nk)*2;
        float g0 = px + (ar[0]*2.f - 0.5f)*0.2f;
        float g1 = py + (ar[1]*2.f - 0.5f)*0.2f;
        g0 = fminf(fmaxf(g0, -1.f), 1.f);
        g1 = fminf(fmaxf(g1, -1.f), 1.f);
        ixs[a] = ((g0 + 1.f)*32.f - 1.f)*0.5f;
        iys[a] = ((g1 + 1.f)*32.f - 1.f)*0.5f;
    }
    const float* pfrow = pf + ((size_t)b*NPTS + idx)*C_;
    float rep2 = 0.f, num[AROUND_], af2[AROUND_];
    #pragma unroll
    for (int a = 0; a < AROUND_; a++){ num[a] = 0.f; af2[a] = 0.f; }
    for (int c = threadIdx.x; c < C_; c += 256){
        float r = pfrow[c];
        rep2 += r*r;
        const float* img = mainx + ((size_t)b*C_ + c)*T_;
        #pragma unroll
        for (int a = 0; a < AROUND_; a++){
            float af = bilin_img(img, ixs[a], iys[a]);
            num[a] += r*af;
            af2[a] += af*af;
            semb[a*C_ + c] = bilin_pe(pe, ixs[a], iys[a], c);
        }
    }
    float vals[11];
    vals[0] = rep2;
    #pragma unroll
    for (int a = 0; a < AROUND_; a++){ vals[1+a] = num[a]; vals[6+a] = af2[a]; }
    for (int v = 0; v < 11; v++){
        red[threadIdx.x] = vals[v];
        __syncthreads();
        for (int s = 128; s; s >>= 1){
            if (threadIdx.x < s) red[threadIdx.x] += red[threadIdx.x + s];
            __syncthreads();
        }
        if (threadIdx.x == 0) res[v] = red[0];
        __syncthreads();
    }
    if (threadIdx.x == 0){
        float rn = fmaxf(sqrtf(res[0]), 1e-8f);
        float s[AROUND_]; float mx = -1e30f;
        for (int a = 0; a < AROUND_; a++){
            s[a] = res[1+a] / (rn * fmaxf(sqrtf(res[6+a]), 1e-8f));
            mx = fmaxf(mx, s[a]);
        }
        float ss = 0.f;
        for (int a = 0; a < AROUND_; a++){ s[a] = expf(s[a] - mx); ss += s[a]; }
        for (int a = 0; a < AROUND_; a++) sw[a] = s[a] / ss;
    }
    __syncthreads();
    float w0 = sw[0], w1 = sw[1], w2 = sw[2], w3 = sw[3], w4 = sw[4];
    for (int c = threadIdx.x; c < C_; c += 256){
        float o = pfrow[c] + mqrow[c];
        o += semb[0*C_ + c]*w0 + semb[1*C_ + c]*w1 + semb[2*C_ + c]*w2
           + semb[3*C_ + c]*w3 + semb[4*C_ + c]*w4;
        memo[((size_t)b*10 + rowBase + nk)*C_ + c] = o;
    }
}

// ---------------- tgt init ----------------
__global__ void tgt_init_kernel(const float* __restrict__ mainx, const float* __restrict__ mq,
                                const float* __restrict__ pe, float* __restrict__ tgt){
    __shared__ float tile[32][33];
    int c0 = blockIdx.x*32, t0 = blockIdx.y*32, b = blockIdx.z;
    for (int i = threadIdx.y; i < 32; i += 8)
        tile[i][threadIdx.x] = mainx[((size_t)b*C_ + c0 + i)*T_ + t0 + threadIdx.x];
    __syncthreads();
    for (int i = threadIdx.y; i < 32; i += 8){
        int t = t0 + i, c = c0 + threadIdx.x;
        tgt[((size_t)b*T_ + t)*C_ + c] = tile[threadIdx.x][i] + mq[c] + pe[(size_t)t*C_ + c];
    }
}

// ---------------- row softmax over 1024 ----------------
__global__ void softmax_kernel(float* __restrict__ S){
    size_t row = blockIdx.x;
    float* p = S + row*T_;
    int t = threadIdx.x;
    float v[4];
    float mx = -1e30f;
    #pragma unroll
    for (int i = 0; i < 4; i++){ v[i] = p[t + i*256]; mx = fmaxf(mx, v[i]); }
    __shared__ float red[256];
    red[t] = mx; __syncthreads();
    for (int s = 128; s; s >>= 1){
        if (t < s) red[t] = fmaxf(red[t], red[t + s]);
        __syncthreads();
    }
    mx = red[0]; __syncthreads();
    float sum = 0.f;
    #pragma unroll
    for (int i = 0; i < 4; i++){ v[i] = expf(v[i] - mx); sum += v[i]; }
    red[t] = sum; __syncthreads();
    for (int s = 128; s; s >>= 1){
        if (t < s) red[t] += red[t + s];
        __syncthreads();
    }
    float inv = 1.f / red[0];
    #pragma unroll
    for (int i = 0; i < 4; i++) p[t + i*256] = v[i]*inv;
}

// ---------------- cross-attention (10 keys) ----------------
__global__ void ca_attn_kernel(const float* __restrict__ q, const float* __restrict__ kv,
                               float* __restrict__ out){
    int bh = blockIdx.y, b = bh >> 3, h = bh & 7;
    int i = blockIdx.x*256 + threadIdx.x;
    __shared__ float Ks[10][96];
    __shared__ float Vsm[10][96];
    for (int idx = threadIdx.x; idx < 960; idx += 256){
        int j = idx / 96, d = idx % 96;
        Ks[j][d]  = kv[((size_t)b*10 + j)*(2*C_) + h*HD_ + d];
        Vsm[j][d] = kv[((size_t)b*10 + j)*(2*C_) + C_ + h*HD_ + d];
    }
    __syncthreads();
    const float* qr = q + ((size_t)b*T_ + i)*C_ + h*HD_;
    float s[10];
    #pragma unroll
    for (int j = 0; j < 10; j++) s[j] = 0.f;
    for (int d = 0; d < HD_; d++){
        float qd = qr[d];
        #pragma unroll
        for (int j = 0; j < 10; j++) s[j] += qd * Ks[j][d];
    }
    const float scale = 0.10206207261596577f;
    float mx = -1e30f;
    #pragma unroll
    for (int j = 0; j < 10; j++){ s[j] *= scale; mx = fmaxf(mx, s[j]); }
    float sum = 0.f;
    #pragma unroll
    for (int j = 0; j < 10; j++){ s[j] = expf(s[j] - mx); sum += s[j]; }
    float inv = 1.f / sum;
    #pragma unroll
    for (int j = 0; j < 10; j++) s[j] *= inv;
    float* orow = out + ((size_t)b*T_ + i)*C_ + h*HD_;
    for (int d = 0; d < HD_; d++){
        float o = 0.f;
        #pragma unroll
        for (int j = 0; j < 10; j++) o += s[j] * Vsm[j][d];
        orow[d] = o;
    }
}

// ---------------- residual add + layernorm ----------------
__global__ void add_ln_kernel(float* __restrict__ tgt, const float* __restrict__ resid,
                              const float* __restrict__ w, const float* __restrict__ bb){
    int row = blockIdx.x, t = threadIdx.x;
    float* p = tgt + (size_t)row*C_;
    const float* r = resid + (size_t)row*C_;
    float v[3];
    float sum = 0.f;
    #pragma unroll
    for (int i = 0; i < 3; i++){ v[i] = p[t + i*256] + r[t + i*256]; sum += v[i]; }
    __shared__ float red[256];
    red[t] = sum; __syncthreads();
    for (int s = 128; s; s >>= 1){ if (t < s) red[t] += red[t + s]; __syncthreads(); }
    float m = red[0] * (1.f/768.f);
    __syncthreads();
    float s2 = 0.f;
    #pragma unroll
    for (int i = 0; i < 3; i++){ float d = v[i] - m; s2 += d*d; }
    red[t] = s2; __syncthreads();
    for (int s = 128; s; s >>= 1){ if (t < s) red[t] += red[t + s]; __syncthreads(); }
    float var = red[0] * (1.f/768.f);
    float rstd = rsqrtf(var + 1e-5f);
    #pragma unroll
    for (int i = 0; i < 3; i++){
        int c = t + i*256;
        p[c] = (v[i] - m)*rstd*w[c] + bb[c];
    }
}

// ---------------- final transpose ----------------
__global__ void transpose_out_kernel(const float* __restrict__ tgt, float* __restrict__ out){
    __shared__ float tile[32][33];
    int c0 = blockIdx.x*32, t0 = blockIdx.y*32, b = blockIdx.z;
    for (int i = threadIdx.y; i < 32; i += 8)
        tile[i][threadIdx.x] = tgt[((size_t)b*T_ + t0 + i)*C_ + c0 + threadIdx.x];
    __syncthreads();
    for (int i = threadIdx.y; i < 32; i += 8)
        out[((size_t)b*C_ + c0 + i)*T_ + t0 + threadIdx.x] = tile[threadIdx.x][i];
}

// ---------------- launch ----------------
extern "C" void kernel_launch(void* const* d_in, const int* in_sizes, int n_in,
                              void* d_out, int out_size){
    const float* mainx      = (const float*)d_in[0];
    const float* others[2]  = {(const float*)d_in[1], (const float*)d_in[2]};
    const float* pe         = (const float*)d_in[3];
    const float* mq         = (const float*)d_in[4];
    const float* s_w1       = (const float*)d_in[5];
    const float* s_b1       = (const float*)d_in[6];
    const float* s_w2       = (const float*)d_in[7];
    const float* s_b2       = (const float*)d_in[8];
    const float* sa_in_w    = (const float*)d_in[9];
    const float* sa_in_b    = (const float*)d_in[10];
    const float* sa_out_w   = (const float*)d_in[11];
    const float* sa_out_b   = (const float*)d_in[12];
    const float* ca_in_w    = (const float*)d_in[13];
    const float* ca_in_b    = (const float*)d_in[14];
    const float* ca_out_w   = (const float*)d_in[15];
    const float* ca_out_b   = (const float*)d_in[16];
    const float* ff1_w      = (const float*)d_in[17];
    const float* ff1_b      = (const float*)d_in[18];
    const float* ff2_w      = (const float*)d_in[19];
    const float* ff2_b      = (const float*)d_in[20];
    const float* ln_w       = (const float*)d_in[21];
    const float* ln_b       = (const float*)d_in[22];
    const float* block_rand = (const float*)d_in[23];
    const float* around_rand= (const float*)d_in[24];
    float* out = (float*)d_out;

    float *pf, *hid, *coords, *score, *memb, *tgt, *tmp, *qkv, *Sb, *attn, *ffh, *memkv, *qb;
    int* topidx;
    cudaGetSymbolAddress((void**)&pf,     g_pf);
    cudaGetSymbolAddress((void**)&hid,    g_hid);
    cudaGetSymbolAddress((void**)&coords, g_coords);
    cudaGetSymbolAddress((void**)&score,  g_score);
    cudaGetSymbolAddress((void**)&topidx, g_topidx);
    cudaGetSymbolAddress((void**)&memb,   g_mem);
    cudaGetSymbolAddress((void**)&tgt,    g_tgt);
    cudaGetSymbolAddress((void**)&tmp,    g_tmp);
    cudaGetSymbolAddress((void**)&qkv,    g_qkv);
    cudaGetSymbolAddress((void**)&Sb,     g_S);
    cudaGetSymbolAddress((void**)&attn,   g_attn);
    cudaGetSymbolAddress((void**)&ffh,    g_ffh);
    cudaGetSymbolAddress((void**)&memkv,  g_memkv);
    cudaGetSymbolAddress((void**)&qb,     g_q);

    const float iscale = 0.10206207261596577f;  // 1/sqrt(96)

    // ---- phase A: modalities ----
    for (int i = 0; i < 2; i++){
        sample_kernel<<<B_*NPTS, 256>>>(others[i], block_rand + (size_t)i*B_*32*32*2*2, pf, coords);
        // 3xTF32 exact GEMM (feeds discrete top-k)
        mma_gemm(pf, s_w1, s_b1, hid, B_*NPTS, C_, C_, C_, C_, C_, 1,
                 0,0,0,0,0,0, 1.f, false, true, true);
        score_kernel<<<B_*NPTS, 256>>>(hid, s_w2, s_b2, score);
        topk_kernel<<<B_, 256>>>(score, topidx);
        soft_align_kernel<<<B_*TOPK_, 256>>>(mainx, pe,
                                             around_rand + (size_t)i*B_*AROUND_*TOPK_*2,
                                             mq + (size_t)(i+1)*C_,
                                             pf, coords, topidx, memb, i*TOPK_);
    }

    // ---- tgt init ----
    {
        dim3 g(C_/32, T_/32, B_); dim3 bl(32, 8);
        tgt_init_kernel<<<g, bl>>>(mainx, mq, pe, tgt);
    }

    // ---- decoder layers ----
    for (int l = 0; l < L_; l++){
        // self-attention
        mma_gemm(tgt, sa_in_w + (size_t)l*C_*3*C_, sa_in_b + (size_t)l*3*C_, qkv,
                 B_*T_, 3*C_, C_, C_, 3*C_, 3*C_, 1, 0,0,0,0,0,0, 1.f, false, false, false);
        // scores: per (b,h) Q·K^T * scale  (NT, batched over z=64)
        mma_gemm(qkv, qkv + C_, nullptr, Sb, T_, T_, HD_, 3*C_, 3*C_, T_, B_*NHEAD_,
                 (long)T_*3*C_, HD_, (long)T_*3*C_, HD_,
                 (long)NHEAD_*T_*T_, (long)T_*T_, iscale, true, false, false);
        softmax_kernel<<<B_*NHEAD_*T_, 256>>>(Sb);
        // O = att @ V (NN, batched)
        mma_gemm(Sb, qkv + 2*C_, nullptr, attn, T_, HD_, T_, T_, 3*C_, C_, B_*NHEAD_,
                 (long)NHEAD_*T_*T_, (long)T_*T_, (long)T_*3*C_, HD_,
                 (long)T_*C_, HD_, 1.f, false, false, false);
        mma_gemm(attn, sa_out_w + (size_t)l*C_*C_, sa_out_b + (size_t)l*C_, tmp,
                 B_*T_, C_, C_, C_, C_, C_, 1, 0,0,0,0,0,0, 1.f, false, false, false);
        add_ln_kernel<<<B_*T_, 256>>>(tgt, tmp, ln_w + (size_t)(l*3+0)*C_, ln_b + (size_t)(l*3+0)*C_);

        // cross-attention
        mma_gemm(tgt, ca_in_w + (size_t)l*C_*3*C_, ca_in_b + (size_t)l*3*C_, qb,
                 B_*T_, C_, C_, C_, 3*C_, C_, 1, 0,0,0,0,0,0, 1.f, false, false, false);
        mma_gemm(memb, ca_in_w + (size_t)l*C_*3*C_ + C_, ca_in_b + (size_t)l*3*C_ + C_, memkv,
                 B_*10, 2*C_, C_, C_, 3*C_, 2*C_, 1, 0,0,0,0,0,0, 1.f, false, false, false);
        { dim3 g(T_/256, B_*NHEAD_); ca_attn_kernel<<<g, 256>>>(qb, memkv, attn); }
        mma_gemm(attn, ca_out_w + (size_t)l*C_*C_, ca_out_b + (size_t)l*C_, tmp,
                 B_*T_, C_, C_, C_, C_, C_, 1, 0,0,0,0,0,0, 1.f, false, false, false);
        add_ln_kernel<<<B_*T_, 256>>>(tgt, tmp, ln_w + (size_t)(l*3+1)*C_, ln_b + (size_t)(l*3+1)*C_);

        // feed-forward
        mma_gemm(tgt, ff1_w + (size_t)l*C_*FF_, ff1_b + (size_t)l*FF_, ffh,
                 B_*T_, FF_, C_, C_, FF_, FF_, 1, 0,0,0,0,0,0, 1.f, false, false, true);
        mma_gemm(ffh, ff2_w + (size_t)l*FF_*C_, ff2_b + (size_t)l*C_, tmp,
                 B_*T_, C_, FF_, FF_, C_, C_, 1, 0,0,0,0,0,0, 1.f, false, false, false);
        add_ln_kernel<<<B_*T_, 256>>>(tgt, tmp, ln_w + (size_t)(l*3+2)*C_, ln_b + (size_t)(l*3+2)*C_);
    }

    // ---- output transpose ----
    {
        dim3 g(C_/32, T_/32, B_); dim3 bl(32, 8);
        transpose_out_kernel<<<g, bl>>>(tgt, out);
    }
}

// round 4
// speedup vs baseline: 2.4273x; 1.0645x over previous
#include <cuda_runtime.h>
#include <cuda_bf16.h>
#include <math.h>
#include <stdint.h>

// ---------------- constants ----------------
#define B_   8
#define C_   768
#define H_   32
#define W_   32
#define T_   1024          // H*W
#define L_   2
#define FF_  3072
#define NPTS 2048          // PH*PW*K
#define TOPK_ 5
#define AROUND_ 5
#define NHEAD_ 8
#define HD_  96

// ---------------- scratch (device globals; allocation-free) ----------------
__device__ float g_pf    [(size_t)B_*NPTS*C_];
__device__ float g_hid   [(size_t)B_*NPTS*C_];   // also reused as xT scratch
__device__ float g_coords[(size_t)B_*NPTS*2];
__device__ float g_score [(size_t)B_*NPTS];
__device__ int   g_topidx[B_*TOPK_];
__device__ float g_mem   [(size_t)B_*10*C_];
__device__ float g_tgt   [(size_t)B_*T_*C_];
__device__ float g_tmp   [(size_t)B_*T_*C_];
__device__ float g_qkv   [(size_t)B_*T_*3*C_];
__device__ float g_attn  [(size_t)B_*T_*C_];
__device__ float g_ffh   [(size_t)B_*T_*FF_];
__device__ float g_memkv [(size_t)B_*10*2*C_];
__device__ float g_q     [(size_t)B_*T_*C_];

// ---------------- tf32 helpers ----------------
__device__ __forceinline__ float f2tf32(float x){
    uint32_t u; asm("cvt.rna.tf32.f32 %0, %1;" : "=r"(u) : "f"(x));
    return __uint_as_float(u);
}
__device__ __forceinline__ void mma8(float* d, const float* a, const float* b){
    asm volatile("mma.sync.aligned.m16n8k8.row.col.f32.tf32.tf32.f32 "
        "{%0,%1,%2,%3},{%4,%5,%6,%7},{%8,%9},{%0,%1,%2,%3};\n"
        : "+f"(d[0]), "+f"(d[1]), "+f"(d[2]), "+f"(d[3])
        : "r"(__float_as_uint(a[0])), "r"(__float_as_uint(a[1])),
          "r"(__float_as_uint(a[2])), "r"(__float_as_uint(a[3])),
          "r"(__float_as_uint(b[0])), "r"(__float_as_uint(b[1])));
}

// ---------------- TF32 MMA GEMM (dense projections) ----------------
template<bool NT, bool EXACT, bool RELU>
__global__ __launch_bounds__(256)
void mma_gemm_kernel(const float* __restrict__ A, const float* __restrict__ B,
                     const float* __restrict__ bias, float* __restrict__ C,
                     int M, int N, int K, int lda, int ldb, int ldc,
                     long sA1, long sA2, long sB1, long sB2, long sC1, long sC2,
                     float scale)
{
    const int PAD = 136;
    const int SEG = (EXACT ? 4 : 2) * 16 * PAD;
    __shared__ float smem[(EXACT ? 1 : 2) * ((EXACT ? 4 : 2) * 16 * PAD)];

    int z = blockIdx.z, zb = z >> 3, zh = z & 7;
    A += (size_t)zb * sA1 + (size_t)zh * sA2;
    B += (size_t)zb * sB1 + (size_t)zh * sB2;
    C += (size_t)zb * sC1 + (size_t)zh * sC2;

    int tid = threadIdx.x, lane = tid & 31, warp = tid >> 5;
    int gid = lane >> 2, tig = lane & 3;
    int wm = warp >> 2, wn = warp & 3;
    int row0 = blockIdx.y * 128, col0 = blockIdx.x * 128;

    float acc[4][4][4];
    #pragma unroll
    for (int i = 0; i < 4; i++)
        #pragma unroll
        for (int j = 0; j < 4; j++)
            #pragma unroll
            for (int r = 0; r < 4; r++) acc[i][j][r] = 0.f;

    float4 ra[2], rb[2];
    const float4 zero4 = make_float4(0.f,0.f,0.f,0.f);

    auto gload = [&](int k0){
        #pragma unroll
        for (int i = 0; i < 2; i++){
            int idx = tid + 256*i;
            int arow = idx >> 2, ac4 = idx & 3;
            int gr = row0 + arow;
            ra[i] = (gr < M) ? *(const float4*)(A + (size_t)gr*lda + k0 + ac4*4) : zero4;
            if (NT){
                int bn = idx >> 2, bc4 = idx & 3;
                int gn = col0 + bn;
                rb[i] = (gn < N) ? *(const float4*)(B + (size_t)gn*ldb + k0 + bc4*4) : zero4;
            } else {
                int brow = idx >> 5, bc4 = idx & 31;
                int gc = col0 + bc4*4;
                rb[i] = (gc < N) ? *(const float4*)(B + (size_t)(k0 + brow)*ldb + gc) : zero4;
            }
        }
    };

    auto sstore = [&](int buf){
        float* Ahi = smem + buf*SEG;
        float* Bhi = Ahi + 16*PAD;
        float* Alo = Ahi + 2*16*PAD;
        float* Blo = Ahi + 3*16*PAD;
        #pragma unroll
        for (int i = 0; i < 2; i++){
            int idx = tid + 256*i;
            int arow = idx >> 2, ac4 = idx & 3;
            const float* pa = (const float*)&ra[i];
            #pragma unroll
            for (int j = 0; j < 4; j++){
                float v = pa[j], h = f2tf32(v);
                Ahi[(ac4*4 + j)*PAD + arow] = h;
                if (EXACT) Alo[(ac4*4 + j)*PAD + arow] = f2tf32(v - h);
            }
            const float* pb = (const float*)&rb[i];
            if (NT){
                int bn = idx >> 2, bc4 = idx & 3;
                #pragma unroll
                for (int j = 0; j < 4; j++){
                    float v = pb[j], h = f2tf32(v);
                    Bhi[(bc4*4 + j)*PAD + bn] = h;
                    if (EXACT) Blo[(bc4*4 + j)*PAD + bn] = f2tf32(v - h);
                }
            } else {
                int brow = idx >> 5, bc4 = idx & 31;
                float4 h4, l4;
                h4.x = f2tf32(pb[0]); h4.y = f2tf32(pb[1]);
                h4.z = f2tf32(pb[2]); h4.w = f2tf32(pb[3]);
                *(float4*)&Bhi[brow*PAD + bc4*4] = h4;
                if (EXACT){
                    l4.x = f2tf32(pb[0]-h4.x); l4.y = f2tf32(pb[1]-h4.y);
                    l4.z = f2tf32(pb[2]-h4.z); l4.w = f2tf32(pb[3]-h4.w);
                    *(float4*)&Blo[brow*PAD + bc4*4] = l4;
                }
            }
        }
    };

    auto compute = [&](int buf){
        const float* Ahi = smem + buf*SEG;
        const float* Bhi = Ahi + 16*PAD;
        const float* Alo = Ahi + 2*16*PAD;
        const float* Blo = Ahi + 3*16*PAD;
        #pragma unroll
        for (int kk = 0; kk < 16; kk += 8){
            int k1 = (kk + tig)*PAD, k2 = (kk + tig + 4)*PAD;
            float ah[4][4], bh[4][2], al[4][4], bl[4][2];
            #pragma unroll
            for (int ma = 0; ma < 4; ma++){
                int m = wm*64 + ma*16 + gid;
                ah[ma][0] = Ahi[k1 + m];     ah[ma][1] = Ahi[k1 + m + 8];
                ah[ma][2] = Ahi[k2 + m];     ah[ma][3] = Ahi[k2 + m + 8];
                if (EXACT){
                    al[ma][0] = Alo[k1 + m]; al[ma][1] = Alo[k1 + m + 8];
                    al[ma][2] = Alo[k2 + m]; al[ma][3] = Alo[k2 + m + 8];
                }
            }
            #pragma unroll
            for (int na = 0; na < 4; na++){
                int n = wn*32 + na*8 + gid;
                bh[na][0] = Bhi[k1 + n]; bh[na][1] = Bhi[k2 + n];
                if (EXACT){ bl[na][0] = Blo[k1 + n]; bl[na][1] = Blo[k2 + n]; }
            }
            #pragma unroll
            for (int ma = 0; ma < 4; ma++)
                #pragma unroll
                for (int na = 0; na < 4; na++){
                    mma8(acc[ma][na], ah[ma], bh[na]);
                    if (EXACT){
                        mma8(acc[ma][na], ah[ma], bl[na]);
                        mma8(acc[ma][na], al[ma], bh[na]);
                    }
                }
        }
    };

    int nk = K / 16;
    if (EXACT){
        for (int it = 0; it < nk; it++){
            if (it == 0) gload(0);
            if (it > 0) __syncthreads();
            sstore(0);
            __syncthreads();
            if (it + 1 < nk) gload((it + 1)*16);
            compute(0);
        }
    } else {
        gload(0); sstore(0); __syncthreads();
        for (int it = 0; it < nk; it++){
            if (it + 1 < nk) gload((it + 1)*16);
            compute(it & 1);
            if (it + 1 < nk){ __syncthreads(); sstore((it + 1)&1); __syncthreads(); }
        }
    }

    #pragma unroll
    for (int ma = 0; ma < 4; ma++){
        int r0 = row0 + wm*64 + ma*16 + gid;
        #pragma unroll
        for (int na = 0; na < 4; na++){
            int c = col0 + wn*32 + na*8 + 2*tig;
            if (c >= N) continue;
            float b0 = bias ? bias[c] : 0.f;
            float b1 = bias ? bias[c+1] : 0.f;
            float x0 = acc[ma][na][0]*scale + b0;
            float x1 = acc[ma][na][1]*scale + b1;
            float x2 = acc[ma][na][2]*scale + b0;
            float x3 = acc[ma][na][3]*scale + b1;
            if (RELU){
                x0 = fmaxf(x0, 0.f); x1 = fmaxf(x1, 0.f);
                x2 = fmaxf(x2, 0.f); x3 = fmaxf(x3, 0.f);
            }
            if (r0 < M){ float2 o = make_float2(x0, x1); *(float2*)&C[(size_t)r0*ldc + c] = o; }
            if (r0 + 8 < M){ float2 o = make_float2(x2, x3); *(float2*)&C[(size_t)(r0+8)*ldc + c] = o; }
        }
    }
}

static void mma_gemm(const float* A, const float* B, const float* bias, float* C,
                     int M, int N, int K, int lda, int ldb, int ldc, int gz,
                     long sA1, long sA2, long sB1, long sB2, long sC1, long sC2,
                     float scale, bool nt, bool exact, bool relu){
    dim3 grid((N + 127)/128, (M + 127)/128, gz);
    if (nt)
        mma_gemm_kernel<true,false,false><<<grid,256>>>(A,B,bias,C,M,N,K,lda,ldb,ldc,sA1,sA2,sB1,sB2,sC1,sC2,scale);
    else if (exact)
        mma_gemm_kernel<false,true,true><<<grid,256>>>(A,B,bias,C,M,N,K,lda,ldb,ldc,sA1,sA2,sB1,sB2,sC1,sC2,scale);
    else if (relu)
        mma_gemm_kernel<false,false,true><<<grid,256>>>(A,B,bias,C,M,N,K,lda,ldb,ldc,sA1,sA2,sB1,sB2,sC1,sC2,scale);
    else
        mma_gemm_kernel<false,false,false><<<grid,256>>>(A,B,bias,C,M,N,K,lda,ldb,ldc,sA1,sA2,sB1,sB2,sC1,sC2,scale);
}

// ---------------- flash attention (tf32 MMA, online softmax) ----------------
// one block = one (b,h) x 128-row q tile; 8 warps x 16 rows.
// smem: Ks [96][136], Vs [128][104], Ps [128][136]  (dynamic, 175104 B)
#define FA_PADK 136
#define FA_PADV 104
#define FA_LOG2E 1.4426950408889634f

__global__ __launch_bounds__(256, 1)
void flash_attn_kernel(const float* __restrict__ qkv, float* __restrict__ out){
    extern __shared__ float sm[];
    float* Ks = sm;                    // 96*136
    float* Vs = Ks + 96*FA_PADK;       // 128*104
    float* Ps = Vs + 128*FA_PADV;      // 128*136

    int qt = blockIdx.x, bh = blockIdx.y, b = bh >> 3, h = bh & 7;
    int tid = threadIdx.x, lane = tid & 31, warp = tid >> 5;
    int gid = lane >> 2, tig = lane & 3;
    int m0 = warp * 16;
    int q0 = qt * 128;
    const float iscale = 0.10206207261596577f;   // 1/sqrt(96)

    // Q fragments in registers (scaled); 12 k-steps of 8
    float qf[12][4];
    {
        const float* Qa = qkv + (size_t)(b*T_ + q0 + m0 + gid)*(3*C_) + h*HD_;
        const float* Qb = Qa + 8*(3*C_);
        #pragma unroll
        for (int kk = 0; kk < 12; kk++){
            qf[kk][0] = Qa[kk*8 + tig]     * iscale;
            qf[kk][1] = Qb[kk*8 + tig]     * iscale;
            qf[kk][2] = Qa[kk*8 + tig + 4] * iscale;
            qf[kk][3] = Qb[kk*8 + tig + 4] * iscale;
        }
    }

    float oacc[12][4];
    #pragma unroll
    for (int i = 0; i < 12; i++)
        #pragma unroll
        for (int j = 0; j < 4; j++) oacc[i][j] = 0.f;
    float mrow0 = -1e30f, mrow1 = -1e30f, lrow0 = 0.f, lrow1 = 0.f;

    for (int kt = 0; kt < 8; kt++){
        __syncthreads();
        // cooperative K,V chunk load (128 seq rows x 96)
        {
            const float* Kb = qkv + (size_t)(b*T_ + kt*128)*(3*C_) + C_ + h*HD_;
            const float* Vb = Kb + C_;
            for (int idx = tid; idx < 128*24; idx += 256){
                int r = idx / 24, c4 = idx % 24;
                float4 kv4 = *(const float4*)(Kb + (size_t)r*(3*C_) + c4*4);
                Ks[(c4*4+0)*FA_PADK + r] = kv4.x;
                Ks[(c4*4+1)*FA_PADK + r] = kv4.y;
                Ks[(c4*4+2)*FA_PADK + r] = kv4.z;
                Ks[(c4*4+3)*FA_PADK + r] = kv4.w;
                float4 vv4 = *(const float4*)(Vb + (size_t)r*(3*C_) + c4*4);
                *(float4*)&Vs[r*FA_PADV + c4*4] = vv4;
            }
        }
        __syncthreads();

        // S = (Q*iscale) K^T, 16 rows x 128 cols per warp
        float sacc[16][4];
        #pragma unroll
        for (int nf = 0; nf < 16; nf++)
            #pragma unroll
            for (int j = 0; j < 4; j++) sacc[nf][j] = 0.f;
        #pragma unroll
        for (int kk = 0; kk < 12; kk++){
            int k1 = (kk*8 + tig)*FA_PADK, k2 = (kk*8 + tig + 4)*FA_PADK;
            #pragma unroll
            for (int nf = 0; nf < 16; nf++){
                float bfr[2] = { Ks[k1 + nf*8 + gid], Ks[k2 + nf*8 + gid] };
                mma8(sacc[nf], qf[kk], bfr);
            }
        }

        // online softmax (rows gid, gid+8 within warp; reduce across quad)
        float rm0 = -1e30f, rm1 = -1e30f;
        #pragma unroll
        for (int nf = 0; nf < 16; nf++){
            rm0 = fmaxf(rm0, fmaxf(sacc[nf][0], sacc[nf][1]));
            rm1 = fmaxf(rm1, fmaxf(sacc[nf][2], sacc[nf][3]));
        }
        rm0 = fmaxf(rm0, __shfl_xor_sync(0xffffffffu, rm0, 1));
        rm0 = fmaxf(rm0, __shfl_xor_sync(0xffffffffu, rm0, 2));
        rm1 = fmaxf(rm1, __shfl_xor_sync(0xffffffffu, rm1, 1));
        rm1 = fmaxf(rm1, __shfl_xor_sync(0xffffffffu, rm1, 2));
        float mn0 = fmaxf(mrow0, rm0), mn1 = fmaxf(mrow1, rm1);
        float al0 = exp2f((mrow0 - mn0)*FA_LOG2E);
        float al1 = exp2f((mrow1 - mn1)*FA_LOG2E);
        mrow0 = mn0; mrow1 = mn1;
        float rs0 = 0.f, rs1 = 0.f;
        #pragma unroll
        for (int nf = 0; nf < 16; nf++){
            float p0 = exp2f((sacc[nf][0] - mn0)*FA_LOG2E);
            float p1 = exp2f((sacc[nf][1] - mn0)*FA_LOG2E);
            float p2 = exp2f((sacc[nf][2] - mn1)*FA_LOG2E);
            float p3 = exp2f((sacc[nf][3] - mn1)*FA_LOG2E);
            sacc[nf][0] = p0; sacc[nf][1] = p1; sacc[nf][2] = p2; sacc[nf][3] = p3;
            rs0 += p0 + p1; rs1 += p2 + p3;
        }
        rs0 += __shfl_xor_sync(0xffffffffu, rs0, 1);
        rs0 += __shfl_xor_sync(0xffffffffu, rs0, 2);
        rs1 += __shfl_xor_sync(0xffffffffu, rs1, 1);
        rs1 += __shfl_xor_sync(0xffffffffu, rs1, 2);
        lrow0 = lrow0*al0 + rs0;
        lrow1 = lrow1*al1 + rs1;
        #pragma unroll
        for (int nf = 0; nf < 12; nf++){
            oacc[nf][0] *= al0; oacc[nf][1] *= al0;
            oacc[nf][2] *= al1; oacc[nf][3] *= al1;
        }

        // store P to warp-private smem region [k=seq][m]
        #pragma unroll
        for (int nf = 0; nf < 16; nf++){
            int c = nf*8 + 2*tig;
            Ps[(size_t)c*FA_PADK     + m0 + gid]     = sacc[nf][0];
            Ps[(size_t)(c+1)*FA_PADK + m0 + gid]     = sacc[nf][1];
            Ps[(size_t)c*FA_PADK     + m0 + gid + 8] = sacc[nf][2];
            Ps[(size_t)(c+1)*FA_PADK + m0 + gid + 8] = sacc[nf][3];
        }
        __syncwarp();

        // O += P @ V  (k = 128 seq, n = 96)
        #pragma unroll
        for (int kk = 0; kk < 16; kk++){
            int k1 = (kk*8 + tig)*FA_PADK, k2 = (kk*8 + tig + 4)*FA_PADK;
            float pa[4] = { Ps[k1 + m0 + gid], Ps[k1 + m0 + gid + 8],
                            Ps[k2 + m0 + gid], Ps[k2 + m0 + gid + 8] };
            int v1 = (kk*8 + tig)*FA_PADV, v2 = (kk*8 + tig + 4)*FA_PADV;
            #pragma unroll
            for (int nf = 0; nf < 12; nf++){
                float vb2[2] = { Vs[v1 + nf*8 + gid], Vs[v2 + nf*8 + gid] };
                mma8(oacc[nf], pa, vb2);
            }
        }
    }

    // epilogue: divide by l, write out
    float inv0 = 1.f / lrow0, inv1 = 1.f / lrow1;
    size_t r0 = (size_t)(b*T_ + q0 + m0 + gid);
    #pragma unroll
    for (int nf = 0; nf < 12; nf++){
        int col = h*HD_ + nf*8 + 2*tig;
        float2 o0 = make_float2(oacc[nf][0]*inv0, oacc[nf][1]*inv0);
        float2 o1 = make_float2(oacc[nf][2]*inv1, oacc[nf][3]*inv1);
        *(float2*)&out[r0*C_ + col]       = o0;
        *(float2*)&out[(r0 + 8)*C_ + col] = o1;
    }
}

// ---------------- bilinear helpers ----------------
__device__ __forceinline__ float bilin_img(const float* __restrict__ img, float ix, float iy){
    float x0f = floorf(ix), y0f = floorf(iy);
    int x0 = (int)x0f, y0 = (int)y0f;
    float wx1 = ix - x0f, wy1 = iy - y0f;
    float wx0 = 1.f - wx1, wy0 = 1.f - wy1;
    float v = 0.f;
    bool vx0 = (x0 >= 0) & (x0 < 32);
    bool vx1 = (x0 + 1 >= 0) & (x0 + 1 < 32);
    bool vy0 = (y0 >= 0) & (y0 < 32);
    bool vy1 = (y0 + 1 >= 0) & (y0 + 1 < 32);
    if (vx0 & vy0) v += img[y0*32 + x0]         * wx0 * wy0;
    if (vx1 & vy0) v += img[y0*32 + x0 + 1]     * wx1 * wy0;
    if (vx0 & vy1) v += img[(y0+1)*32 + x0]     * wx0 * wy1;
    if (vx1 & vy1) v += img[(y0+1)*32 + x0 + 1] * wx1 * wy1;
    return v;
}
__device__ __forceinline__ float bilin_pe(const float* __restrict__ pe, float ix, float iy, int c){
    float x0f = floorf(ix), y0f = floorf(iy);
    int x0 = (int)x0f, y0 = (int)y0f;
    float wx1 = ix - x0f, wy1 = iy - y0f;
    float wx0 = 1.f - wx1, wy0 = 1.f - wy1;
    float v = 0.f;
    bool vx0 = (x0 >= 0) & (x0 < 32);
    bool vx1 = (x0 + 1 >= 0) & (x0 + 1 < 32);
    bool vy0 = (y0 >= 0) & (y0 < 32);
    bool vy1 = (y0 + 1 >= 0) & (y0 + 1 < 32);
    if (vx0 & vy0) v += pe[((size_t)(y0*32 + x0))*C_ + c]         * wx0 * wy0;
    if (vx1 & vy0) v += pe[((size_t)(y0*32 + x0 + 1))*C_ + c]     * wx1 * wy0;
    if (vx0 & vy1) v += pe[((size_t)((y0+1)*32 + x0))*C_ + c]     * wx0 * wy1;
    if (vx1 & vy1) v += pe[((size_t)((y0+1)*32 + x0 + 1))*C_ + c] * wx1 * wy1;
    return v;
}

// ---------------- transpose x [B,C,T] -> xT [B,T,C] ----------------
__global__ void transpose_in_kernel(const float* __restrict__ x, float* __restrict__ xT){
    __shared__ float tile[32][33];
    int c0 = blockIdx.x*32, t0 = blockIdx.y*32, b = blockIdx.z;
    for (int i = threadIdx.y; i < 32; i += 8)
        tile[i][threadIdx.x] = x[((size_t)b*C_ + c0 + i)*T_ + t0 + threadIdx.x];
    __syncthreads();
    for (int i = threadIdx.y; i < 32; i += 8)
        xT[((size_t)b*T_ + t0 + i)*C_ + c0 + threadIdx.x] = tile[threadIdx.x][i];
}

// ---------------- blockwise sampling from xT (coalesced) ----------------
__global__ void sample_kernel(const float* __restrict__ xT, const float* __restrict__ brand,
                              float* __restrict__ pf, float* __restrict__ coords){
    int p0 = blockIdx.x * 16;               // 16 points per block (same batch)
    __shared__ int   sidx[16][4];
    __shared__ float swt [16][4];
    int tid = threadIdx.x;
    if (tid < 16){
        int bn = p0 + tid;
        int b  = bn >> 11;
        int n  = bn & 2047;
        int k  = n & 1;
        int pw = (n >> 1) & 31;
        int ph = n >> 6;
        const float bs = 0.0625f;
        const float* br = brand + ((((size_t)b*32 + ph)*32 + pw)*2 + k)*2;
        float gx = br[0]*bs + (-1.0f + ph*bs);
        float gy = br[1]*bs + (-1.0f + pw*bs);
        coords[(size_t)bn*2]     = gx;
        coords[(size_t)bn*2 + 1] = gy;
        float ix = ((gx + 1.0f)*32.0f - 1.0f)*0.5f;
        float iy = ((gy + 1.0f)*32.0f - 1.0f)*0.5f;
        float x0f = floorf(ix), y0f = floorf(iy);
        int x0 = (int)x0f, y0 = (int)y0f;
        float wx1 = ix - x0f, wy1 = iy - y0f;
        float wxs[2] = {1.f - wx1, wx1};
        float wys[2] = {1.f - wy1, wy1};
        #pragma unroll
        for (int j = 0; j < 4; j++){
            int xi = x0 + (j & 1), yi = y0 + (j >> 1);
            bool v = (xi >= 0) & (xi < 32) & (yi >= 0) & (yi < 32);
            sidx[tid][j] = v ? (yi*32 + xi) : 0;
            swt [tid][j] = v ? (wxs[j & 1]*wys[j >> 1]) : 0.f;
        }
    }
    __syncthreads();
    int b = (p0 >> 11);
    const float* base = xT + (size_t)b*T_*C_;
    for (int pt = 0; pt < 16; pt++){
        const float* r0 = base + (size_t)sidx[pt][0]*C_;
        const float* r1 = base + (size_t)sidx[pt][1]*C_;
        const float* r2 = base + (size_t)sidx[pt][2]*C_;
        const float* r3 = base + (size_t)sidx[pt][3]*C_;
        float w0 = swt[pt][0], w1 = swt[pt][1], w2 = swt[pt][2], w3 = swt[pt][3];
        float* dst = pf + (size_t)(p0 + pt)*C_;
        for (int c = tid; c < C_; c += 256)
            dst[c] = r0[c]*w0 + r1[c]*w1 + r2[c]*w2 + r3[c]*w3;
    }
}

// ---------------- score dot ----------------
__global__ void score_kernel(const float* __restrict__ hid, const float* __restrict__ w2,
                             const float* __restrict__ b2, float* __restrict__ score){
    int row = blockIdx.x;
    float p = 0.f;
    for (int c = threadIdx.x; c < C_; c += 256) p += hid[(size_t)row*C_ + c] * w2[c];
    #pragma unroll
    for (int o = 16; o; o >>= 1) p += __shfl_down_sync(0xffffffffu, p, o);
    __shared__ float red[8];
    if ((threadIdx.x & 31) == 0) red[threadIdx.x >> 5] = p;
    __syncthreads();
    if (threadIdx.x == 0){
        float s = 0.f;
        #pragma unroll
        for (int i = 0; i < 8; i++) s += red[i];
        score[row] = s + b2[0];
    }
}

// ---------------- top-5 ----------------
__global__ void topk_kernel(const float* __restrict__ score, int* __restrict__ topidx){
    int b = blockIdx.x;
    __shared__ float sv[2048];
    __shared__ float rv[256];
    __shared__ int   ri[256];
    for (int j = threadIdx.x; j < 2048; j += 256) sv[j] = score[(size_t)b*2048 + j];
    __syncthreads();
    for (int t = 0; t < TOPK_; t++){
        float bv = -1e30f; int bi = 0x7fffffff;
        for (int j = threadIdx.x; j < 2048; j += 256){
            float v = sv[j];
            if (v > bv){ bv = v; bi = j; }
        }
        rv[threadIdx.x] = bv; ri[threadIdx.x] = bi;
        __syncthreads();
        for (int s = 128; s; s >>= 1){
            if (threadIdx.x < s){
                float v2 = rv[threadIdx.x + s]; int i2 = ri[threadIdx.x + s];
                if (v2 > rv[threadIdx.x] || (v2 == rv[threadIdx.x] && i2 < ri[threadIdx.x])){
                    rv[threadIdx.x] = v2; ri[threadIdx.x] = i2;
                }
            }
            __syncthreads();
        }
        if (threadIdx.x == 0){
            topidx[b*TOPK_ + t] = ri[0];
            sv[ri[0]] = -1e30f;
        }
        __syncthreads();
    }
}

// ---------------- soft_align ----------------
__global__ void soft_align_kernel(const float* __restrict__ mainx, const float* __restrict__ pe,
                                  const float* __restrict__ arand, const float* __restrict__ mqrow,
                                  const float* __restrict__ pf, const float* __restrict__ coords,
                                  const int* __restrict__ topidx, float* __restrict__ memo, int rowBase){
    int b  = blockIdx.x / TOPK_;
    int nk = blockIdx.x % TOPK_;
    int idx = topidx[b*TOPK_ + nk];
    float px = coords[((size_t)b*NPTS + idx)*2 + 0];
    float py = coords[((size_t)b*NPTS + idx)*2 + 1];
    __shared__ float semb[AROUND_*C_];
    __shared__ float red[256];
    __shared__ float res[11];
    __shared__ float sw[AROUND_];
    float ixs[AROUND_], iys[AROUND_];
    #pragma unroll
    for (int a = 0; a < AROUND_; a++){
        const float* ar = arand + (((size_t)b*AROUND_ + a)*TOPK_ + nk)*2;
        float g0 = px + (ar[0]*2.f - 0.5f)*0.2f;
        float g1 = py + (ar[1]*2.f - 0.5f)*0.2f;
        g0 = fminf(fmaxf(g0, -1.f), 1.f);
        g1 = fminf(fmaxf(g1, -1.f), 1.f);
        ixs[a] = ((g0 + 1.f)*32.f - 1.f)*0.5f;
        iys[a] = ((g1 + 1.f)*32.f - 1.f)*0.5f;
    }
    const float* pfrow = pf + ((size_t)b*NPTS + idx)*C_;
    float rep2 = 0.f, num[AROUND_], af2[AROUND_];
    #pragma unroll
    for (int a = 0; a < AROUND_; a++){ num[a] = 0.f; af2[a] = 0.f; }
    for (int c = threadIdx.x; c < C_; c += 256){
        float r = pfrow[c];
        rep2 += r*r;
        const float* img = mainx + ((size_t)b*C_ + c)*T_;
        #pragma unroll
        for (int a = 0; a < AROUND_; a++){
            float af = bilin_img(img, ixs[a], iys[a]);
            num[a] += r*af;
            af2[a] += af*af;
            semb[a*C_ + c] = bilin_pe(pe, ixs[a], iys[a], c);
        }
    }
    float vals[11];
    vals[0] = rep2;
    #pragma unroll
    for (int a = 0; a < AROUND_; a++){ vals[1+a] = num[a]; vals[6+a] = af2[a]; }
    for (int v = 0; v < 11; v++){
        red[threadIdx.x] = vals[v];
        __syncthreads();
        for (int s = 128; s; s >>= 1){
            if (threadIdx.x < s) red[threadIdx.x] += red[threadIdx.x + s];
            __syncthreads();
        }
        if (threadIdx.x == 0) res[v] = red[0];
        __syncthreads();
    }
    if (threadIdx.x == 0){
        float rn = fmaxf(sqrtf(res[0]), 1e-8f);
        float s[AROUND_]; float mx = -1e30f;
        for (int a = 0; a < AROUND_; a++){
            s[a] = res[1+a] / (rn * fmaxf(sqrtf(res[6+a]), 1e-8f));
            mx = fmaxf(mx, s[a]);
        }
        float ss = 0.f;
        for (int a = 0; a < AROUND_; a++){ s[a] = expf(s[a] - mx); ss += s[a]; }
        for (int a = 0; a < AROUND_; a++) sw[a] = s[a] / ss;
    }
    __syncthreads();
    float w0 = sw[0], w1 = sw[1], w2 = sw[2], w3 = sw[3], w4 = sw[4];
    for (int c = threadIdx.x; c < C_; c += 256){
        float o = pfrow[c] + mqrow[c];
        o += semb[0*C_ + c]*w0 + semb[1*C_ + c]*w1 + semb[2*C_ + c]*w2
           + semb[3*C_ + c]*w3 + semb[4*C_ + c]*w4;
        memo[((size_t)b*10 + rowBase + nk)*C_ + c] = o;
    }
}

// ---------------- tgt init ----------------
__global__ void tgt_init_kernel(const float* __restrict__ mainx, const float* __restrict__ mq,
                                const float* __restrict__ pe, float* __restrict__ tgt){
    __shared__ float tile[32][33];
    int c0 = blockIdx.x*32, t0 = blockIdx.y*32, b = blockIdx.z;
    for (int i = threadIdx.y; i < 32; i += 8)
        tile[i][threadIdx.x] = mainx[((size_t)b*C_ + c0 + i)*T_ + t0 + threadIdx.x];
    __syncthreads();
    for (int i = threadIdx.y; i < 32; i += 8){
        int t = t0 + i, c = c0 + threadIdx.x;
        tgt[((size_t)b*T_ + t)*C_ + c] = tile[threadIdx.x][i] + mq[c] + pe[(size_t)t*C_ + c];
    }
}

// ---------------- cross-attention (10 keys) ----------------
__global__ void ca_attn_kernel(const float* __restrict__ q, const float* __restrict__ kv,
                               float* __restrict__ out){
    int bh = blockIdx.y, b = bh >> 3, h = bh & 7;
    int i = blockIdx.x*256 + threadIdx.x;
    __shared__ float Ks[10][96];
    __shared__ float Vsm[10][96];
    for (int idx = threadIdx.x; idx < 960; idx += 256){
        int j = idx / 96, d = idx % 96;
        Ks[j][d]  = kv[((size_t)b*10 + j)*(2*C_) + h*HD_ + d];
        Vsm[j][d] = kv[((size_t)b*10 + j)*(2*C_) + C_ + h*HD_ + d];
    }
    __syncthreads();
    const float* qr = q + ((size_t)b*T_ + i)*C_ + h*HD_;
    float s[10];
    #pragma unroll
    for (int j = 0; j < 10; j++) s[j] = 0.f;
    for (int d = 0; d < HD_; d++){
        float qd = qr[d];
        #pragma unroll
        for (int j = 0; j < 10; j++) s[j] += qd * Ks[j][d];
    }
    const float scale = 0.10206207261596577f;
    float mx = -1e30f;
    #pragma unroll
    for (int j = 0; j < 10; j++){ s[j] *= scale; mx = fmaxf(mx, s[j]); }
    float sum = 0.f;
    #pragma unroll
    for (int j = 0; j < 10; j++){ s[j] = expf(s[j] - mx); sum += s[j]; }
    float inv = 1.f / sum;
    #pragma unroll
    for (int j = 0; j < 10; j++) s[j] *= inv;
    float* orow = out + ((size_t)b*T_ + i)*C_ + h*HD_;
    for (int d = 0; d < HD_; d++){
        float o = 0.f;
        #pragma unroll
        for (int j = 0; j < 10; j++) o += s[j] * Vsm[j][d];
        orow[d] = o;
    }
}

// ---------------- residual add + layernorm ----------------
__global__ void add_ln_kernel(float* __restrict__ tgt, const float* __restrict__ resid,
                              const float* __restrict__ w, const float* __restrict__ bb){
    int row = blockIdx.x, t = threadIdx.x;
    float* p = tgt + (size_t)row*C_;
    const float* r = resid + (size_t)row*C_;
    float v[3];
    float sum = 0.f;
    #pragma unroll
    for (int i = 0; i < 3; i++){ v[i] = p[t + i*256] + r[t + i*256]; sum += v[i]; }
    __shared__ float red[256];
    red[t] = sum; __syncthreads();
    for (int s = 128; s; s >>= 1){ if (t < s) red[t] += red[t + s]; __syncthreads(); }
    float m = red[0] * (1.f/768.f);
    __syncthreads();
    float s2 = 0.f;
    #pragma unroll
    for (int i = 0; i < 3; i++){ float d = v[i] - m; s2 += d*d; }
    red[t] = s2; __syncthreads();
    for (int s = 128; s; s >>= 1){ if (t < s) red[t] += red[t + s]; __syncthreads(); }
    float var = red[0] * (1.f/768.f);
    float rstd = rsqrtf(var + 1e-5f);
    #pragma unroll
    for (int i = 0; i < 3; i++){
        int c = t + i*256;
        p[c] = (v[i] - m)*rstd*w[c] + bb[c];
    }
}

// ---------------- final transpose ----------------
__global__ void transpose_out_kernel(const float* __restrict__ tgt, float* __restrict__ out){
    __shared__ float tile[32][33];
    int c0 = blockIdx.x*32, t0 = blockIdx.y*32, b = blockIdx.z;
    for (int i = threadIdx.y; i < 32; i += 8)
        tile[i][threadIdx.x] = tgt[((size_t)b*T_ + t0 + i)*C_ + c0 + threadIdx.x];
    __syncthreads();
    for (int i = threadIdx.y; i < 32; i += 8)
        out[((size_t)b*C_ + c0 + i)*T_ + t0 + threadIdx.x] = tile[threadIdx.x][i];
}

// ---------------- launch ----------------
extern "C" void kernel_launch(void* const* d_in, const int* in_sizes, int n_in,
                              void* d_out, int out_size){
    const float* mainx      = (const float*)d_in[0];
    const float* others[2]  = {(const float*)d_in[1], (const float*)d_in[2]};
    const float* pe         = (const float*)d_in[3];
    const float* mq         = (const float*)d_in[4];
    const float* s_w1       = (const float*)d_in[5];
    const float* s_b1       = (const float*)d_in[6];
    const float* s_w2       = (const float*)d_in[7];
    const float* s_b2       = (const float*)d_in[8];
    const float* sa_in_w    = (const float*)d_in[9];
    const float* sa_in_b    = (const float*)d_in[10];
    const float* sa_out_w   = (const float*)d_in[11];
    const float* sa_out_b   = (const float*)d_in[12];
    const float* ca_in_w    = (const float*)d_in[13];
    const float* ca_in_b    = (const float*)d_in[14];
    const float* ca_out_w   = (const float*)d_in[15];
    const float* ca_out_b   = (const float*)d_in[16];
    const float* ff1_w      = (const float*)d_in[17];
    const float* ff1_b      = (const float*)d_in[18];
    const float* ff2_w      = (const float*)d_in[19];
    const float* ff2_b      = (const float*)d_in[20];
    const float* ln_w       = (const float*)d_in[21];
    const float* ln_b       = (const float*)d_in[22];
    const float* block_rand = (const float*)d_in[23];
    const float* around_rand= (const float*)d_in[24];
    float* out = (float*)d_out;

    float *pf, *hid, *coords, *score, *memb, *tgt, *tmp, *qkv, *attn, *ffh, *memkv, *qb;
    int* topidx;
    cudaGetSymbolAddress((void**)&pf,     g_pf);
    cudaGetSymbolAddress((void**)&hid,    g_hid);
    cudaGetSymbolAddress((void**)&coords, g_coords);
    cudaGetSymbolAddress((void**)&score,  g_score);
    cudaGetSymbolAddress((void**)&topidx, g_topidx);
    cudaGetSymbolAddress((void**)&memb,   g_mem);
    cudaGetSymbolAddress((void**)&tgt,    g_tgt);
    cudaGetSymbolAddress((void**)&tmp,    g_tmp);
    cudaGetSymbolAddress((void**)&qkv,    g_qkv);
    cudaGetSymbolAddress((void**)&attn,   g_attn);
    cudaGetSymbolAddress((void**)&ffh,    g_ffh);
    cudaGetSymbolAddress((void**)&memkv,  g_memkv);
    cudaGetSymbolAddress((void**)&qb,     g_q);

    const int FA_SMEM = (96*FA_PADK + 128*FA_PADV + 128*FA_PADK) * 4;
    cudaFuncSetAttribute(flash_attn_kernel, cudaFuncAttributeMaxDynamicSharedMemorySize, FA_SMEM);

    // ---- phase A: modalities ----
    for (int i = 0; i < 2; i++){
        // transpose other -> xT (scratch in hid), then coalesced gather
        {
            dim3 g(C_/32, T_/32, B_); dim3 bl(32, 8);
            transpose_in_kernel<<<g, bl>>>(others[i], hid);
        }
        sample_kernel<<<B_*NPTS/16, 256>>>(hid, block_rand + (size_t)i*B_*32*32*2*2, pf, coords);
        // 3xTF32 exact GEMM (feeds discrete top-k)
        mma_gemm(pf, s_w1, s_b1, hid, B_*NPTS, C_, C_, C_, C_, C_, 1,
                 0,0,0,0,0,0, 1.f, false, true, true);
        score_kernel<<<B_*NPTS, 256>>>(hid, s_w2, s_b2, score);
        topk_kernel<<<B_, 256>>>(score, topidx);
        soft_align_kernel<<<B_*TOPK_, 256>>>(mainx, pe,
                                             around_rand + (size_t)i*B_*AROUND_*TOPK_*2,
                                             mq + (size_t)(i+1)*C_,
                                             pf, coords, topidx, memb, i*TOPK_);
    }

    // ---- tgt init ----
    {
        dim3 g(C_/32, T_/32, B_); dim3 bl(32, 8);
        tgt_init_kernel<<<g, bl>>>(mainx, mq, pe, tgt);
    }

    // ---- decoder layers ----
    for (int l = 0; l < L_; l++){
        // self-attention
        mma_gemm(tgt, sa_in_w + (size_t)l*C_*3*C_, sa_in_b + (size_t)l*3*C_, qkv,
                 B_*T_, 3*C_, C_, C_, 3*C_, 3*C_, 1, 0,0,0,0,0,0, 1.f, false, false, false);
        {
            dim3 g(T_/128, B_*NHEAD_);
            flash_attn_kernel<<<g, 256, FA_SMEM>>>(qkv, attn);
        }
        mma_gemm(attn, sa_out_w + (size_t)l*C_*C_, sa_out_b + (size_t)l*C_, tmp,
                 B_*T_, C_, C_, C_, C_, C_, 1, 0,0,0,0,0,0, 1.f, false, false, false);
        add_ln_kernel<<<B_*T_, 256>>>(tgt, tmp, ln_w + (size_t)(l*3+0)*C_, ln_b + (size_t)(l*3+0)*C_);

        // cross-attention
        mma_gemm(tgt, ca_in_w + (size_t)l*C_*3*C_, ca_in_b + (size_t)l*3*C_, qb,
                 B_*T_, C_, C_, C_, 3*C_, C_, 1, 0,0,0,0,0,0, 1.f, false, false, false);
        mma_gemm(memb, ca_in_w + (size_t)l*C_*3*C_ + C_, ca_in_b + (size_t)l*3*C_ + C_, memkv,
                 B_*10, 2*C_, C_, C_, 3*C_, 2*C_, 1, 0,0,0,0,0,0, 1.f, false, false, false);
        { dim3 g(T_/256, B_*NHEAD_); ca_attn_kernel<<<g, 256>>>(qb, memkv, attn); }
        mma_gemm(attn, ca_out_w + (size_t)l*C_*C_, ca_out_b + (size_t)l*C_, tmp,
                 B_*T_, C_, C_, C_, C_, C_, 1, 0,0,0,0,0,0, 1.f, false, false, false);
        add_ln_kernel<<<B_*T_, 256>>>(tgt, tmp, ln_w + (size_t)(l*3+1)*C_, ln_b + (size_t)(l*3+1)*C_);

        // feed-forward
        mma_gemm(tgt, ff1_w + (size_t)l*C_*FF_, ff1_b + (size_t)l*FF_, ffh,
                 B_*T_, FF_, C_, C_, FF_, FF_, 1, 0,0,0,0,0,0, 1.f, false, false, true);
        mma_gemm(ffh, ff2_w + (size_t)l*FF_*C_, ff2_b + (size_t)l*C_, tmp,
                 B_*T_, C_, FF_, FF_, C_, C_, 1, 0,0,0,0,0,0, 1.f, false, false, false);
        add_ln_kernel<<<B_*T_, 256>>>(tgt, tmp, ln_w + (size_t)(l*3+2)*C_, ln_b + (size_t)(l*3+2)*C_);
    }

    // ---- output transpose ----
    {
        dim3 g(C_/32, T_/32, B_); dim3 bl(32, 8);
        transpose_out_kernel<<<g, bl>>>(tgt, out);
    }
}

// round 5
// speedup vs baseline: 2.7069x; 1.1152x over previous
#include <cuda_runtime.h>
#include <cuda_bf16.h>
#include <math.h>
#include <stdint.h>

// ---------------- constants ----------------
#define B_   8
#define C_   768
#define H_   32
#define W_   32
#define T_   1024          // H*W
#define L_   2
#define FF_  3072
#define NPTS 2048          // PH*PW*K
#define TOPK_ 5
#define NCAND 16
#define AROUND_ 5
#define NHEAD_ 8
#define HD_  96

// ---------------- scratch (device globals; allocation-free) ----------------
__device__ float g_pf    [(size_t)B_*NPTS*C_];
__device__ float g_hid   [(size_t)B_*NPTS*C_];   // xT scratch
__device__ float g_coords[(size_t)B_*NPTS*2];
__device__ float g_score [(size_t)B_*NPTS];
__device__ int   g_top16 [B_*NCAND];
__device__ float g_exsc  [B_*NCAND];
__device__ int   g_topidx[B_*TOPK_];
__device__ float g_mem   [(size_t)B_*10*C_];
__device__ float g_tgt   [(size_t)B_*T_*C_];
__device__ float g_tmp   [(size_t)B_*T_*C_];
__device__ float g_qkv   [(size_t)B_*T_*3*C_];
__device__ float g_attn  [(size_t)B_*T_*C_];
__device__ float g_ffh   [(size_t)B_*T_*FF_];
__device__ float g_memkv [(size_t)B_*10*2*C_];
__device__ float g_q     [(size_t)B_*T_*C_];

// ---------------- tf32 helpers ----------------
__device__ __forceinline__ float f2tf32(float x){
    uint32_t u; asm("cvt.rna.tf32.f32 %0, %1;" : "=r"(u) : "f"(x));
    return __uint_as_float(u);
}
__device__ __forceinline__ void mma8(float* d, const float* a, const float* b){
    asm volatile("mma.sync.aligned.m16n8k8.row.col.f32.tf32.tf32.f32 "
        "{%0,%1,%2,%3},{%4,%5,%6,%7},{%8,%9},{%0,%1,%2,%3};\n"
        : "+f"(d[0]), "+f"(d[1]), "+f"(d[2]), "+f"(d[3])
        : "r"(__float_as_uint(a[0])), "r"(__float_as_uint(a[1])),
          "r"(__float_as_uint(a[2])), "r"(__float_as_uint(a[3])),
          "r"(__float_as_uint(b[0])), "r"(__float_as_uint(b[1])));
}

// ---------------- TF32 MMA GEMM ----------------
// SCORE mode: bias+relu, multiply by w2[c], reduce rows, atomicAdd into score;
// no C store (C unused). Otherwise C = scale*A@B + bias (opt relu).
template<bool NT, bool RELU, bool SCORE>
__global__ __launch_bounds__(256)
void mma_gemm_kernel(const float* __restrict__ A, const float* __restrict__ B,
                     const float* __restrict__ bias, float* __restrict__ C,
                     const float* __restrict__ w2, float* __restrict__ score,
                     int M, int N, int K, int lda, int ldb, int ldc,
                     long sA1, long sA2, long sB1, long sB2, long sC1, long sC2,
                     float scale)
{
    const int PAD = 136;
    const int SEG = 2 * 16 * PAD;
    __shared__ float smem[2 * SEG];

    int z = blockIdx.z, zb = z >> 3, zh = z & 7;
    A += (size_t)zb * sA1 + (size_t)zh * sA2;
    B += (size_t)zb * sB1 + (size_t)zh * sB2;
    if (!SCORE) C += (size_t)zb * sC1 + (size_t)zh * sC2;

    int tid = threadIdx.x, lane = tid & 31, warp = tid >> 5;
    int gid = lane >> 2, tig = lane & 3;
    int wm = warp >> 2, wn = warp & 3;
    int row0 = blockIdx.y * 128, col0 = blockIdx.x * 128;

    float acc[4][4][4];
    #pragma unroll
    for (int i = 0; i < 4; i++)
        #pragma unroll
        for (int j = 0; j < 4; j++)
            #pragma unroll
            for (int r = 0; r < 4; r++) acc[i][j][r] = 0.f;

    float4 ra[2], rb[2];
    const float4 zero4 = make_float4(0.f,0.f,0.f,0.f);

    auto gload = [&](int k0){
        #pragma unroll
        for (int i = 0; i < 2; i++){
            int idx = tid + 256*i;
            int arow = idx >> 2, ac4 = idx & 3;
            int gr = row0 + arow;
            ra[i] = (gr < M) ? *(const float4*)(A + (size_t)gr*lda + k0 + ac4*4) : zero4;
            if (NT){
                int bn = idx >> 2, bc4 = idx & 3;
                int gn = col0 + bn;
                rb[i] = (gn < N) ? *(const float4*)(B + (size_t)gn*ldb + k0 + bc4*4) : zero4;
            } else {
                int brow = idx >> 5, bc4 = idx & 31;
                int gc = col0 + bc4*4;
                rb[i] = (gc < N) ? *(const float4*)(B + (size_t)(k0 + brow)*ldb + gc) : zero4;
            }
        }
    };

    auto sstore = [&](int buf){
        float* Ahi = smem + buf*SEG;
        float* Bhi = Ahi + 16*PAD;
        #pragma unroll
        for (int i = 0; i < 2; i++){
            int idx = tid + 256*i;
            int arow = idx >> 2, ac4 = idx & 3;
            const float* pa = (const float*)&ra[i];
            #pragma unroll
            for (int j = 0; j < 4; j++)
                Ahi[(ac4*4 + j)*PAD + arow] = pa[j];
            const float* pb = (const float*)&rb[i];
            if (NT){
                int bn = idx >> 2, bc4 = idx & 3;
                #pragma unroll
                for (int j = 0; j < 4; j++)
                    Bhi[(bc4*4 + j)*PAD + bn] = pb[j];
            } else {
                int brow = idx >> 5, bc4 = idx & 31;
                *(float4*)&Bhi[brow*PAD + bc4*4] = rb[i];
            }
        }
    };

    auto compute = [&](int buf){
        const float* Ahi = smem + buf*SEG;
        const float* Bhi = Ahi + 16*PAD;
        #pragma unroll
        for (int kk = 0; kk < 16; kk += 8){
            int k1 = (kk + tig)*PAD, k2 = (kk + tig + 4)*PAD;
            float ah[4][4], bh[4][2];
            #pragma unroll
            for (int ma = 0; ma < 4; ma++){
                int m = wm*64 + ma*16 + gid;
                ah[ma][0] = Ahi[k1 + m];     ah[ma][1] = Ahi[k1 + m + 8];
                ah[ma][2] = Ahi[k2 + m];     ah[ma][3] = Ahi[k2 + m + 8];
            }
            #pragma unroll
            for (int na = 0; na < 4; na++){
                int n = wn*32 + na*8 + gid;
                bh[na][0] = Bhi[k1 + n]; bh[na][1] = Bhi[k2 + n];
            }
            #pragma unroll
            for (int ma = 0; ma < 4; ma++)
                #pragma unroll
                for (int na = 0; na < 4; na++)
                    mma8(acc[ma][na], ah[ma], bh[na]);
        }
    };

    int nk = K / 16;
    gload(0); sstore(0); __syncthreads();
    for (int it = 0; it < nk; it++){
        if (it + 1 < nk) gload((it + 1)*16);
        compute(it & 1);
        if (it + 1 < nk){ __syncthreads(); sstore((it + 1)&1); __syncthreads(); }
    }

    #pragma unroll
    for (int ma = 0; ma < 4; ma++){
        int r0 = row0 + wm*64 + ma*16 + gid;
        float s0 = 0.f, s1 = 0.f;
        #pragma unroll
        for (int na = 0; na < 4; na++){
            int c = col0 + wn*32 + na*8 + 2*tig;
            if (c >= N) continue;
            float b0 = bias ? bias[c] : 0.f;
            float b1 = bias ? bias[c+1] : 0.f;
            float x0 = acc[ma][na][0]*scale + b0;
            float x1 = acc[ma][na][1]*scale + b1;
            float x2 = acc[ma][na][2]*scale + b0;
            float x3 = acc[ma][na][3]*scale + b1;
            if (RELU || SCORE){
                x0 = fmaxf(x0, 0.f); x1 = fmaxf(x1, 0.f);
                x2 = fmaxf(x2, 0.f); x3 = fmaxf(x3, 0.f);
            }
            if (SCORE){
                float w0 = w2[c], w1 = w2[c+1];
                s0 += x0*w0 + x1*w1;
                s1 += x2*w0 + x3*w1;
            } else {
                if (r0 < M){ float2 o = make_float2(x0, x1); *(float2*)&C[(size_t)r0*ldc + c] = o; }
                if (r0 + 8 < M){ float2 o = make_float2(x2, x3); *(float2*)&C[(size_t)(r0+8)*ldc + c] = o; }
            }
        }
        if (SCORE){
            s0 += __shfl_xor_sync(0xffffffffu, s0, 1);
            s0 += __shfl_xor_sync(0xffffffffu, s0, 2);
            s1 += __shfl_xor_sync(0xffffffffu, s1, 1);
            s1 += __shfl_xor_sync(0xffffffffu, s1, 2);
            if (tig == 0){
                if (r0 < M)     atomicAdd(&score[r0], s0);
                if (r0 + 8 < M) atomicAdd(&score[r0 + 8], s1);
            }
        }
    }
}

static void mma_gemm(const float* A, const float* B, const float* bias, float* C,
                     int M, int N, int K, int lda, int ldb, int ldc, int gz,
                     long sA1, long sA2, long sB1, long sB2, long sC1, long sC2,
                     float scale, bool nt, bool relu){
    dim3 grid((N + 127)/128, (M + 127)/128, gz);
    if (nt)
        mma_gemm_kernel<true,false,false><<<grid,256>>>(A,B,bias,C,nullptr,nullptr,M,N,K,lda,ldb,ldc,sA1,sA2,sB1,sB2,sC1,sC2,scale);
    else if (relu)
        mma_gemm_kernel<false,true,false><<<grid,256>>>(A,B,bias,C,nullptr,nullptr,M,N,K,lda,ldb,ldc,sA1,sA2,sB1,sB2,sC1,sC2,scale);
    else
        mma_gemm_kernel<false,false,false><<<grid,256>>>(A,B,bias,C,nullptr,nullptr,M,N,K,lda,ldb,ldc,sA1,sA2,sB1,sB2,sC1,sC2,scale);
}

static void mma_gemm_score(const float* A, const float* B, const float* bias,
                           const float* w2, float* score, int M, int N, int K,
                           int lda, int ldb){
    dim3 grid((N + 127)/128, (M + 127)/128, 1);
    mma_gemm_kernel<false,true,true><<<grid,256>>>(A,B,bias,nullptr,w2,score,M,N,K,lda,ldb,0,0,0,0,0,0,0,1.f);
}

// ---------------- flash attention (tf32 MMA, online softmax) ----------------
#define FA_PADK 136
#define FA_PADV 104
#define FA_LOG2E 1.4426950408889634f

__global__ __launch_bounds__(256, 1)
void flash_attn_kernel(const float* __restrict__ qkv, float* __restrict__ out){
    extern __shared__ float sm[];
    float* Ks = sm;
    float* Vs = Ks + 96*FA_PADK;
    float* Ps = Vs + 128*FA_PADV;

    int qt = blockIdx.x, bh = blockIdx.y, b = bh >> 3, h = bh & 7;
    int tid = threadIdx.x, lane = tid & 31, warp = tid >> 5;
    int gid = lane >> 2, tig = lane & 3;
    int m0 = warp * 16;
    int q0 = qt * 128;
    const float iscale = 0.10206207261596577f;

    float qf[12][4];
    {
        const float* Qa = qkv + (size_t)(b*T_ + q0 + m0 + gid)*(3*C_) + h*HD_;
        const float* Qb = Qa + 8*(3*C_);
        #pragma unroll
        for (int kk = 0; kk < 12; kk++){
            qf[kk][0] = Qa[kk*8 + tig]     * iscale;
            qf[kk][1] = Qb[kk*8 + tig]     * iscale;
            qf[kk][2] = Qa[kk*8 + tig + 4] * iscale;
            qf[kk][3] = Qb[kk*8 + tig + 4] * iscale;
        }
    }

    float oacc[12][4];
    #pragma unroll
    for (int i = 0; i < 12; i++)
        #pragma unroll
        for (int j = 0; j < 4; j++) oacc[i][j] = 0.f;
    float mrow0 = -1e30f, mrow1 = -1e30f, lrow0 = 0.f, lrow1 = 0.f;

    for (int kt = 0; kt < 8; kt++){
        __syncthreads();
        {
            const float* Kb = qkv + (size_t)(b*T_ + kt*128)*(3*C_) + C_ + h*HD_;
            const float* Vb = Kb + C_;
            for (int idx = tid; idx < 128*24; idx += 256){
                int r = idx / 24, c4 = idx % 24;
                float4 kv4 = *(const float4*)(Kb + (size_t)r*(3*C_) + c4*4);
                Ks[(c4*4+0)*FA_PADK + r] = kv4.x;
                Ks[(c4*4+1)*FA_PADK + r] = kv4.y;
                Ks[(c4*4+2)*FA_PADK + r] = kv4.z;
                Ks[(c4*4+3)*FA_PADK + r] = kv4.w;
                float4 vv4 = *(const float4*)(Vb + (size_t)r*(3*C_) + c4*4);
                *(float4*)&Vs[r*FA_PADV + c4*4] = vv4;
            }
        }
        __syncthreads();

        float sacc[16][4];
        #pragma unroll
        for (int nf = 0; nf < 16; nf++)
            #pragma unroll
            for (int j = 0; j < 4; j++) sacc[nf][j] = 0.f;
        #pragma unroll
        for (int kk = 0; kk < 12; kk++){
            int k1 = (kk*8 + tig)*FA_PADK, k2 = (kk*8 + tig + 4)*FA_PADK;
            #pragma unroll
            for (int nf = 0; nf < 16; nf++){
                float bfr[2] = { Ks[k1 + nf*8 + gid], Ks[k2 + nf*8 + gid] };
                mma8(sacc[nf], qf[kk], bfr);
            }
        }

        float rm0 = -1e30f, rm1 = -1e30f;
        #pragma unroll
        for (int nf = 0; nf < 16; nf++){
            rm0 = fmaxf(rm0, fmaxf(sacc[nf][0], sacc[nf][1]));
            rm1 = fmaxf(rm1, fmaxf(sacc[nf][2], sacc[nf][3]));
        }
        rm0 = fmaxf(rm0, __shfl_xor_sync(0xffffffffu, rm0, 1));
        rm0 = fmaxf(rm0, __shfl_xor_sync(0xffffffffu, rm0, 2));
        rm1 = fmaxf(rm1, __shfl_xor_sync(0xffffffffu, rm1, 1));
        rm1 = fmaxf(rm1, __shfl_xor_sync(0xffffffffu, rm1, 2));
        float mn0 = fmaxf(mrow0, rm0), mn1 = fmaxf(mrow1, rm1);
        float al0 = exp2f((mrow0 - mn0)*FA_LOG2E);
        float al1 = exp2f((mrow1 - mn1)*FA_LOG2E);
        mrow0 = mn0; mrow1 = mn1;
        float rs0 = 0.f, rs1 = 0.f;
        #pragma unroll
        for (int nf = 0; nf < 16; nf++){
            float p0 = exp2f((sacc[nf][0] - mn0)*FA_LOG2E);
            float p1 = exp2f((sacc[nf][1] - mn0)*FA_LOG2E);
            float p2 = exp2f((sacc[nf][2] - mn1)*FA_LOG2E);
            float p3 = exp2f((sacc[nf][3] - mn1)*FA_LOG2E);
            sacc[nf][0] = p0; sacc[nf][1] = p1; sacc[nf][2] = p2; sacc[nf][3] = p3;
            rs0 += p0 + p1; rs1 += p2 + p3;
        }
        rs0 += __shfl_xor_sync(0xffffffffu, rs0, 1);
        rs0 += __shfl_xor_sync(0xffffffffu, rs0, 2);
        rs1 += __shfl_xor_sync(0xffffffffu, rs1, 1);
        rs1 += __shfl_xor_sync(0xffffffffu, rs1, 2);
        lrow0 = lrow0*al0 + rs0;
        lrow1 = lrow1*al1 + rs1;
        #pragma unroll
        for (int nf = 0; nf < 12; nf++){
            oacc[nf][0] *= al0; oacc[nf][1] *= al0;
            oacc[nf][2] *= al1; oacc[nf][3] *= al1;
        }

        #pragma unroll
        for (int nf = 0; nf < 16; nf++){
            int c = nf*8 + 2*tig;
            Ps[(size_t)c*FA_PADK     + m0 + gid]     = sacc[nf][0];
            Ps[(size_t)(c+1)*FA_PADK + m0 + gid]     = sacc[nf][1];
            Ps[(size_t)c*FA_PADK     + m0 + gid + 8] = sacc[nf][2];
            Ps[(size_t)(c+1)*FA_PADK + m0 + gid + 8] = sacc[nf][3];
        }
        __syncwarp();

        #pragma unroll
        for (int kk = 0; kk < 16; kk++){
            int k1 = (kk*8 + tig)*FA_PADK, k2 = (kk*8 + tig + 4)*FA_PADK;
            float pa[4] = { Ps[k1 + m0 + gid], Ps[k1 + m0 + gid + 8],
                            Ps[k2 + m0 + gid], Ps[k2 + m0 + gid + 8] };
            int v1 = (kk*8 + tig)*FA_PADV, v2 = (kk*8 + tig + 4)*FA_PADV;
            #pragma unroll
            for (int nf = 0; nf < 12; nf++){
                float vb2[2] = { Vs[v1 + nf*8 + gid], Vs[v2 + nf*8 + gid] };
                mma8(oacc[nf], pa, vb2);
            }
        }
    }

    float inv0 = 1.f / lrow0, inv1 = 1.f / lrow1;
    size_t r0 = (size_t)(b*T_ + q0 + m0 + gid);
    #pragma unroll
    for (int nf = 0; nf < 12; nf++){
        int col = h*HD_ + nf*8 + 2*tig;
        float2 o0 = make_float2(oacc[nf][0]*inv0, oacc[nf][1]*inv0);
        float2 o1 = make_float2(oacc[nf][2]*inv1, oacc[nf][3]*inv1);
        *(float2*)&out[r0*C_ + col]       = o0;
        *(float2*)&out[(r0 + 8)*C_ + col] = o1;
    }
}

// ---------------- bilinear helpers ----------------
__device__ __forceinline__ float bilin_img(const float* __restrict__ img, float ix, float iy){
    float x0f = floorf(ix), y0f = floorf(iy);
    int x0 = (int)x0f, y0 = (int)y0f;
    float wx1 = ix - x0f, wy1 = iy - y0f;
    float wx0 = 1.f - wx1, wy0 = 1.f - wy1;
    float v = 0.f;
    bool vx0 = (x0 >= 0) & (x0 < 32);
    bool vx1 = (x0 + 1 >= 0) & (x0 + 1 < 32);
    bool vy0 = (y0 >= 0) & (y0 < 32);
    bool vy1 = (y0 + 1 >= 0) & (y0 + 1 < 32);
    if (vx0 & vy0) v += img[y0*32 + x0]         * wx0 * wy0;
    if (vx1 & vy0) v += img[y0*32 + x0 + 1]     * wx1 * wy0;
    if (vx0 & vy1) v += img[(y0+1)*32 + x0]     * wx0 * wy1;
    if (vx1 & vy1) v += img[(y0+1)*32 + x0 + 1] * wx1 * wy1;
    return v;
}
__device__ __forceinline__ float bilin_pe(const float* __restrict__ pe, float ix, float iy, int c){
    float x0f = floorf(ix), y0f = floorf(iy);
    int x0 = (int)x0f, y0 = (int)y0f;
    float wx1 = ix - x0f, wy1 = iy - y0f;
    float wx0 = 1.f - wx1, wy0 = 1.f - wy1;
    float v = 0.f;
    bool vx0 = (x0 >= 0) & (x0 < 32);
    bool vx1 = (x0 + 1 >= 0) & (x0 + 1 < 32);
    bool vy0 = (y0 >= 0) & (y0 < 32);
    bool vy1 = (y0 + 1 >= 0) & (y0 + 1 < 32);
    if (vx0 & vy0) v += pe[((size_t)(y0*32 + x0))*C_ + c]         * wx0 * wy0;
    if (vx1 & vy0) v += pe[((size_t)(y0*32 + x0 + 1))*C_ + c]     * wx1 * wy0;
    if (vx0 & vy1) v += pe[((size_t)((y0+1)*32 + x0))*C_ + c]     * wx0 * wy1;
    if (vx1 & vy1) v += pe[((size_t)((y0+1)*32 + x0 + 1))*C_ + c] * wx1 * wy1;
    return v;
}

// ---------------- transpose x [B,C,T] -> xT [B,T,C] ----------------
__global__ void transpose_in_kernel(const float* __restrict__ x, float* __restrict__ xT){
    __shared__ float tile[32][33];
    int c0 = blockIdx.x*32, t0 = blockIdx.y*32, b = blockIdx.z;
    for (int i = threadIdx.y; i < 32; i += 8)
        tile[i][threadIdx.x] = x[((size_t)b*C_ + c0 + i)*T_ + t0 + threadIdx.x];
    __syncthreads();
    for (int i = threadIdx.y; i < 32; i += 8)
        xT[((size_t)b*T_ + t0 + i)*C_ + c0 + threadIdx.x] = tile[threadIdx.x][i];
}

// ---------------- blockwise sampling from xT ----------------
__global__ void sample_kernel(const float* __restrict__ xT, const float* __restrict__ brand,
                              float* __restrict__ pf, float* __restrict__ coords){
    int p0 = blockIdx.x * 16;
    __shared__ int   sidx[16][4];
    __shared__ float swt [16][4];
    int tid = threadIdx.x;
    if (tid < 16){
        int bn = p0 + tid;
        int b  = bn >> 11;
        int n  = bn & 2047;
        int k  = n & 1;
        int pw = (n >> 1) & 31;
        int ph = n >> 6;
        const float bs = 0.0625f;
        const float* br = brand + ((((size_t)b*32 + ph)*32 + pw)*2 + k)*2;
        float gx = br[0]*bs + (-1.0f + ph*bs);
        float gy = br[1]*bs + (-1.0f + pw*bs);
        coords[(size_t)bn*2]     = gx;
        coords[(size_t)bn*2 + 1] = gy;
        float ix = ((gx + 1.0f)*32.0f - 1.0f)*0.5f;
        float iy = ((gy + 1.0f)*32.0f - 1.0f)*0.5f;
        float x0f = floorf(ix), y0f = floorf(iy);
        int x0 = (int)x0f, y0 = (int)y0f;
        float wx1 = ix - x0f, wy1 = iy - y0f;
        float wxs[2] = {1.f - wx1, wx1};
        float wys[2] = {1.f - wy1, wy1};
        #pragma unroll
        for (int j = 0; j < 4; j++){
            int xi = x0 + (j & 1), yi = y0 + (j >> 1);
            bool v = (xi >= 0) & (xi < 32) & (yi >= 0) & (yi < 32);
            sidx[tid][j] = v ? (yi*32 + xi) : 0;
            swt [tid][j] = v ? (wxs[j & 1]*wys[j >> 1]) : 0.f;
        }
    }
    __syncthreads();
    int b = (p0 >> 11);
    const float* base = xT + (size_t)b*T_*C_;
    for (int pt = 0; pt < 16; pt++){
        const float* r0 = base + (size_t)sidx[pt][0]*C_;
        const float* r1 = base + (size_t)sidx[pt][1]*C_;
        const float* r2 = base + (size_t)sidx[pt][2]*C_;
        const float* r3 = base + (size_t)sidx[pt][3]*C_;
        float w0 = swt[pt][0], w1 = swt[pt][1], w2 = swt[pt][2], w3 = swt[pt][3];
        float* dst = pf + (size_t)(p0 + pt)*C_;
        for (int c = tid; c < C_; c += 256)
            dst[c] = r0[c]*w0 + r1[c]*w1 + r2[c]*w2 + r3[c]*w3;
    }
}

// ---------------- zero score ----------------
__global__ void zero_score_kernel(float* __restrict__ score){
    int i = blockIdx.x*256 + threadIdx.x;
    if (i < B_*NPTS) score[i] = 0.f;
}

// ---------------- top-K (approx candidates) ----------------
__global__ void topk_kernel(const float* __restrict__ score, int* __restrict__ topidx, int K){
    int b = blockIdx.x;
    __shared__ float sv[2048];
    __shared__ float rv[256];
    __shared__ int   ri[256];
    for (int j = threadIdx.x; j < 2048; j += 256) sv[j] = score[(size_t)b*2048 + j];
    __syncthreads();
    for (int t = 0; t < K; t++){
        float bv = -1e30f; int bi = 0x7fffffff;
        for (int j = threadIdx.x; j < 2048; j += 256){
            float v = sv[j];
            if (v > bv){ bv = v; bi = j; }
        }
        rv[threadIdx.x] = bv; ri[threadIdx.x] = bi;
        __syncthreads();
        for (int s = 128; s; s >>= 1){
            if (threadIdx.x < s){
                float v2 = rv[threadIdx.x + s]; int i2 = ri[threadIdx.x + s];
                if (v2 > rv[threadIdx.x] || (v2 == rv[threadIdx.x] && i2 < ri[threadIdx.x])){
                    rv[threadIdx.x] = v2; ri[threadIdx.x] = i2;
                }
            }
            __syncthreads();
        }
        if (threadIdx.x == 0){
            topidx[b*K + t] = ri[0];
            sv[ri[0]] = -1e30f;
        }
        __syncthreads();
    }
}

// ---------------- exact fp32 rescore of candidates ----------------
__global__ __launch_bounds__(256)
void rescore_kernel(const float* __restrict__ pf, const float* __restrict__ W1,
                    const float* __restrict__ b1, const float* __restrict__ w2,
                    const int* __restrict__ cand, float* __restrict__ exsc){
    int b = blockIdx.x >> 4, c = blockIdx.x & 15;
    int idx = cand[b*NCAND + c];
    __shared__ float spf[C_];
    int tid = threadIdx.x;
    for (int i = tid; i < C_; i += 256) spf[i] = pf[((size_t)b*NPTS + idx)*C_ + i];
    __syncthreads();
    float a0 = b1[tid], a1 = b1[tid+256], a2 = b1[tid+512];
    for (int k = 0; k < C_; k++){
        float v = spf[k];
        const float* w = W1 + (size_t)k*C_;
        a0 += v * w[tid];
        a1 += v * w[tid+256];
        a2 += v * w[tid+512];
    }
    float p = fmaxf(a0,0.f)*w2[tid] + fmaxf(a1,0.f)*w2[tid+256] + fmaxf(a2,0.f)*w2[tid+512];
    #pragma unroll
    for (int o = 16; o; o >>= 1) p += __shfl_down_sync(0xffffffffu, p, o);
    __shared__ float red[8];
    if ((tid & 31) == 0) red[tid >> 5] = p;
    __syncthreads();
    if (tid == 0){
        float s = 0.f;
        #pragma unroll
        for (int i = 0; i < 8; i++) s += red[i];
        exsc[b*NCAND + c] = s;
    }
}

// ---------------- final exact top-5 over candidates ----------------
__global__ void final_top5_kernel(const float* __restrict__ exsc, const int* __restrict__ cand,
                                  int* __restrict__ topidx){
    int b = blockIdx.x;
    if (threadIdx.x == 0){
        float s[NCAND]; int id[NCAND];
        for (int i = 0; i < NCAND; i++){ s[i] = exsc[b*NCAND + i]; id[i] = cand[b*NCAND + i]; }
        for (int t = 0; t < TOPK_; t++){
            int bi = 0;
            float bv = -1e30f; int bid = 0x7fffffff;
            for (int i = 0; i < NCAND; i++){
                if (s[i] > bv || (s[i] == bv && id[i] < bid)){ bv = s[i]; bid = id[i]; bi = i; }
            }
            topidx[b*TOPK_ + t] = id[bi];
            s[bi] = -1e30f;
        }
    }
}

// ---------------- soft_align ----------------
__global__ void soft_align_kernel(const float* __restrict__ mainx, const float* __restrict__ pe,
                                  const float* __restrict__ arand, const float* __restrict__ mqrow,
                                  const float* __restrict__ pf, const float* __restrict__ coords,
                                  const int* __restrict__ topidx, float* __restrict__ memo, int rowBase){
    int b  = blockIdx.x / TOPK_;
    int nk = blockIdx.x % TOPK_;
    int idx = topidx[b*TOPK_ + nk];
    float px = coords[((size_t)b*NPTS + idx)*2 + 0];
    float py = coords[((size_t)b*NPTS + idx)*2 + 1];
    __shared__ float semb[AROUND_*C_];
    __shared__ float red[256];
    __shared__ float res[11];
    __shared__ float sw[AROUND_];
    float ixs[AROUND_], iys[AROUND_];
    #pragma unroll
    for (int a = 0; a < AROUND_; a++){
        const float* ar = arand + (((size_t)b*AROUND_ + a)*TOPK_ + nk)*2;
        float g0 = px + (ar[0]*2.f - 0.5f)*0.2f;
        float g1 = py + (ar[1]*2.f - 0.5f)*0.2f;
        g0 = fminf(fmaxf(g0, -1.f), 1.f);
        g1 = fminf(fmaxf(g1, -1.f), 1.f);
        ixs[a] = ((g0 + 1.f)*32.f - 1.f)*0.5f;
        iys[a] = ((g1 + 1.f)*32.f - 1.f)*0.5f;
    }
    const float* pfrow = pf + ((size_t)b*NPTS + idx)*C_;
    float rep2 = 0.f, num[AROUND_], af2[AROUND_];
    #pragma unroll
    for (int a = 0; a < AROUND_; a++){ num[a] = 0.f; af2[a] = 0.f; }
    for (int c = threadIdx.x; c < C_; c += 256){
        float r = pfrow[c];
        rep2 += r*r;
        const float* img = mainx + ((size_t)b*C_ + c)*T_;
        #pragma unroll
        for (int a = 0; a < AROUND_; a++){
            float af = bilin_img(img, ixs[a], iys[a]);
            num[a] += r*af;
            af2[a] += af*af;
            semb[a*C_ + c] = bilin_pe(pe, ixs[a], iys[a], c);
        }
    }
    float vals[11];
    vals[0] = rep2;
    #pragma unroll
    for (int a = 0; a < AROUND_; a++){ vals[1+a] = num[a]; vals[6+a] = af2[a]; }
    for (int v = 0; v < 11; v++){
        red[threadIdx.x] = vals[v];
        __syncthreads();
        for (int s = 128; s; s >>= 1){
            if (threadIdx.x < s) red[threadIdx.x] += red[threadIdx.x + s];
            __syncthreads();
        }
        if (threadIdx.x == 0) res[v] = red[0];
        __syncthreads();
    }
    if (threadIdx.x == 0){
        float rn = fmaxf(sqrtf(res[0]), 1e-8f);
        float s[AROUND_]; float mx = -1e30f;
        for (int a = 0; a < AROUND_; a++){
            s[a] = res[1+a] / (rn * fmaxf(sqrtf(res[6+a]), 1e-8f));
            mx = fmaxf(mx, s[a]);
        }
        float ss = 0.f;
        for (int a = 0; a < AROUND_; a++){ s[a] = expf(s[a] - mx); ss += s[a]; }
        for (int a = 0; a < AROUND_; a++) sw[a] = s[a] / ss;
    }
    __syncthreads();
    float w0 = sw[0], w1 = sw[1], w2 = sw[2], w3 = sw[3], w4 = sw[4];
    for (int c = threadIdx.x; c < C_; c += 256){
        float o = pfrow[c] + mqrow[c];
        o += semb[0*C_ + c]*w0 + semb[1*C_ + c]*w1 + semb[2*C_ + c]*w2
           + semb[3*C_ + c]*w3 + semb[4*C_ + c]*w4;
        memo[((size_t)b*10 + rowBase + nk)*C_ + c] = o;
    }
}

// ---------------- tgt init ----------------
__global__ void tgt_init_kernel(const float* __restrict__ mainx, const float* __restrict__ mq,
                                const float* __restrict__ pe, float* __restrict__ tgt){
    __shared__ float tile[32][33];
    int c0 = blockIdx.x*32, t0 = blockIdx.y*32, b = blockIdx.z;
    for (int i = threadIdx.y; i < 32; i += 8)
        tile[i][threadIdx.x] = mainx[((size_t)b*C_ + c0 + i)*T_ + t0 + threadIdx.x];
    __syncthreads();
    for (int i = threadIdx.y; i < 32; i += 8){
        int t = t0 + i, c = c0 + threadIdx.x;
        tgt[((size_t)b*T_ + t)*C_ + c] = tile[threadIdx.x][i] + mq[c] + pe[(size_t)t*C_ + c];
    }
}

// ---------------- cross-attention (10 keys) ----------------
__global__ void ca_attn_kernel(const float* __restrict__ q, const float* __restrict__ kv,
                               float* __restrict__ out){
    int bh = blockIdx.y, b = bh >> 3, h = bh & 7;
    int i = blockIdx.x*256 + threadIdx.x;
    __shared__ float Ks[10][96];
    __shared__ float Vsm[10][96];
    for (int idx = threadIdx.x; idx < 960; idx += 256){
        int j = idx / 96, d = idx % 96;
        Ks[j][d]  = kv[((size_t)b*10 + j)*(2*C_) + h*HD_ + d];
        Vsm[j][d] = kv[((size_t)b*10 + j)*(2*C_) + C_ + h*HD_ + d];
    }
    __syncthreads();
    const float* qr = q + ((size_t)b*T_ + i)*C_ + h*HD_;
    float s[10];
    #pragma unroll
    for (int j = 0; j < 10; j++) s[j] = 0.f;
    for (int d = 0; d < HD_; d++){
        float qd = qr[d];
        #pragma unroll
        for (int j = 0; j < 10; j++) s[j] += qd * Ks[j][d];
    }
    const float scale = 0.10206207261596577f;
    float mx = -1e30f;
    #pragma unroll
    for (int j = 0; j < 10; j++){ s[j] *= scale; mx = fmaxf(mx, s[j]); }
    float sum = 0.f;
    #pragma unroll
    for (int j = 0; j < 10; j++){ s[j] = expf(s[j] - mx); sum += s[j]; }
    float inv = 1.f / sum;
    #pragma unroll
    for (int j = 0; j < 10; j++) s[j] *= inv;
    float* orow = out + ((size_t)b*T_ + i)*C_ + h*HD_;
    for (int d = 0; d < HD_; d++){
        float o = 0.f;
        #pragma unroll
        for (int j = 0; j < 10; j++) o += s[j] * Vsm[j][d];
        orow[d] = o;
    }
}

// ---------------- residual add + layernorm ----------------
__global__ void add_ln_kernel(float* __restrict__ tgt, const float* __restrict__ resid,
                              const float* __restrict__ w, const float* __restrict__ bb){
    int row = blockIdx.x, t = threadIdx.x;
    float* p = tgt + (size_t)row*C_;
    const float* r = resid + (size_t)row*C_;
    float v[3];
    float sum = 0.f;
    #pragma unroll
    for (int i = 0; i < 3; i++){ v[i] = p[t + i*256] + r[t + i*256]; sum += v[i]; }
    __shared__ float red[256];
    red[t] = sum; __syncthreads();
    for (int s = 128; s; s >>= 1){ if (t < s) red[t] += red[t + s]; __syncthreads(); }
    float m = red[0] * (1.f/768.f);
    __syncthreads();
    float s2 = 0.f;
    #pragma unroll
    for (int i = 0; i < 3; i++){ float d = v[i] - m; s2 += d*d; }
    red[t] = s2; __syncthreads();
    for (int s = 128; s; s >>= 1){ if (t < s) red[t] += red[t + s]; __syncthreads(); }
    float var = red[0] * (1.f/768.f);
    float rstd = rsqrtf(var + 1e-5f);
    #pragma unroll
    for (int i = 0; i < 3; i++){
        int c = t + i*256;
        p[c] = (v[i] - m)*rstd*w[c] + bb[c];
    }
}

// ---------------- final transpose ----------------
__global__ void transpose_out_kernel(const float* __restrict__ tgt, float* __restrict__ out){
    __shared__ float tile[32][33];
    int c0 = blockIdx.x*32, t0 = blockIdx.y*32, b = blockIdx.z;
    for (int i = threadIdx.y; i < 32; i += 8)
        tile[i][threadIdx.x] = tgt[((size_t)b*T_ + t0 + i)*C_ + c0 + threadIdx.x];
    __syncthreads();
    for (int i = threadIdx.y; i < 32; i += 8)
        out[((size_t)b*C_ + c0 + i)*T_ + t0 + threadIdx.x] = tile[threadIdx.x][i];
}

// ---------------- launch ----------------
extern "C" void kernel_launch(void* const* d_in, const int* in_sizes, int n_in,
                              void* d_out, int out_size){
    const float* mainx      = (const float*)d_in[0];
    const float* others[2]  = {(const float*)d_in[1], (const float*)d_in[2]};
    const float* pe         = (const float*)d_in[3];
    const float* mq         = (const float*)d_in[4];
    const float* s_w1       = (const float*)d_in[5];
    const float* s_b1       = (const float*)d_in[6];
    const float* s_w2       = (const float*)d_in[7];
    const float* s_b2       = (const float*)d_in[8];
    const float* sa_in_w    = (const float*)d_in[9];
    const float* sa_in_b    = (const float*)d_in[10];
    const float* sa_out_w   = (const float*)d_in[11];
    const float* sa_out_b   = (const float*)d_in[12];
    const float* ca_in_w    = (const float*)d_in[13];
    const float* ca_in_b    = (const float*)d_in[14];
    const float* ca_out_w   = (const float*)d_in[15];
    const float* ca_out_b   = (const float*)d_in[16];
    const float* ff1_w      = (const float*)d_in[17];
    const float* ff1_b      = (const float*)d_in[18];
    const float* ff2_w      = (const float*)d_in[19];
    const float* ff2_b      = (const float*)d_in[20];
    const float* ln_w       = (const float*)d_in[21];
    const float* ln_b       = (const float*)d_in[22];
    const float* block_rand = (const float*)d_in[23];
    const float* around_rand= (const float*)d_in[24];
    float* out = (float*)d_out;

    float *pf, *hid, *coords, *score, *memb, *tgt, *tmp, *qkv, *attn, *ffh, *memkv, *qb, *exsc;
    int *topidx, *top16;
    cudaGetSymbolAddress((void**)&pf,     g_pf);
    cudaGetSymbolAddress((void**)&hid,    g_hid);
    cudaGetSymbolAddress((void**)&coords, g_coords);
    cudaGetSymbolAddress((void**)&score,  g_score);
    cudaGetSymbolAddress((void**)&top16,  g_top16);
    cudaGetSymbolAddress((void**)&exsc,   g_exsc);
    cudaGetSymbolAddress((void**)&topidx, g_topidx);
    cudaGetSymbolAddress((void**)&memb,   g_mem);
    cudaGetSymbolAddress((void**)&tgt,    g_tgt);
    cudaGetSymbolAddress((void**)&tmp,    g_tmp);
    cudaGetSymbolAddress((void**)&qkv,    g_qkv);
    cudaGetSymbolAddress((void**)&attn,   g_attn);
    cudaGetSymbolAddress((void**)&ffh,    g_ffh);
    cudaGetSymbolAddress((void**)&memkv,  g_memkv);
    cudaGetSymbolAddress((void**)&qb,     g_q);

    const int FA_SMEM = (96*FA_PADK + 128*FA_PADV + 128*FA_PADK) * 4;
    cudaFuncSetAttribute(flash_attn_kernel, cudaFuncAttributeMaxDynamicSharedMemorySize, FA_SMEM);

    // ---- phase A: modalities ----
    for (int i = 0; i < 2; i++){
        {
            dim3 g(C_/32, T_/32, B_); dim3 bl(32, 8);
            transpose_in_kernel<<<g, bl>>>(others[i], hid);
        }
        sample_kernel<<<B_*NPTS/16, 256>>>(hid, block_rand + (size_t)i*B_*32*32*2*2, pf, coords);
        zero_score_kernel<<<(B_*NPTS + 255)/256, 256>>>(score);
        // approx score (1x tf32, fused dot in epilogue)
        mma_gemm_score(pf, s_w1, s_b1, s_w2, score, B_*NPTS, C_, C_, C_, C_);
        topk_kernel<<<B_, 256>>>(score, top16, NCAND);
        rescore_kernel<<<B_*NCAND, 256>>>(pf, s_w1, s_b1, s_w2, top16, exsc);
        final_top5_kernel<<<B_, 32>>>(exsc, top16, topidx);
        soft_align_kernel<<<B_*TOPK_, 256>>>(mainx, pe,
                                             around_rand + (size_t)i*B_*AROUND_*TOPK_*2,
                                             mq + (size_t)(i+1)*C_,
                                             pf, coords, topidx, memb, i*TOPK_);
    }

    // ---- tgt init ----
    {
        dim3 g(C_/32, T_/32, B_); dim3 bl(32, 8);
        tgt_init_kernel<<<g, bl>>>(mainx, mq, pe, tgt);
    }

    // ---- decoder layers ----
    for (int l = 0; l < L_; l++){
        mma_gemm(tgt, sa_in_w + (size_t)l*C_*3*C_, sa_in_b + (size_t)l*3*C_, qkv,
                 B_*T_, 3*C_, C_, C_, 3*C_, 3*C_, 1, 0,0,0,0,0,0, 1.f, false, false);
        {
            dim3 g(T_/128, B_*NHEAD_);
            flash_attn_kernel<<<g, 256, FA_SMEM>>>(qkv, attn);
        }
        mma_gemm(attn, sa_out_w + (size_t)l*C_*C_, sa_out_b + (size_t)l*C_, tmp,
                 B_*T_, C_, C_, C_, C_, C_, 1, 0,0,0,0,0,0, 1.f, false, false);
        add_ln_kernel<<<B_*T_, 256>>>(tgt, tmp, ln_w + (size_t)(l*3+0)*C_, ln_b + (size_t)(l*3+0)*C_);

        mma_gemm(tgt, ca_in_w + (size_t)l*C_*3*C_, ca_in_b + (size_t)l*3*C_, qb,
                 B_*T_, C_, C_, C_, 3*C_, C_, 1, 0,0,0,0,0,0, 1.f, false, false);
        mma_gemm(memb, ca_in_w + (size_t)l*C_*3*C_ + C_, ca_in_b + (size_t)l*3*C_ + C_, memkv,
                 B_*10, 2*C_, C_, C_, 3*C_, 2*C_, 1, 0,0,0,0,0,0, 1.f, false, false);
        { dim3 g(T_/256, B_*NHEAD_); ca_attn_kernel<<<g, 256>>>(qb, memkv, attn); }
        mma_gemm(attn, ca_out_w + (size_t)l*C_*C_, ca_out_b + (size_t)l*C_, tmp,
                 B_*T_, C_, C_, C_, C_, C_, 1, 0,0,0,0,0,0, 1.f, false, false);
        add_ln_kernel<<<B_*T_, 256>>>(tgt, tmp, ln_w + (size_t)(l*3+1)*C_, ln_b + (size_t)(l*3+1)*C_);

        mma_gemm(tgt, ff1_w + (size_t)l*C_*FF_, ff1_b + (size_t)l*FF_, ffh,
                 B_*T_, FF_, C_, C_, FF_, FF_, 1, 0,0,0,0,0,0, 1.f, false, true);
        mma_gemm(ffh, ff2_w + (size_t)l*FF_*C_, ff2_b + (size_t)l*C_, tmp,
                 B_*T_, C_, FF_, FF_, C_, C_, 1, 0,0,0,0,0,0, 1.f, false, false);
        add_ln_kernel<<<B_*T_, 256>>>(tgt, tmp, ln_w + (size_t)(l*3+2)*C_, ln_b + (size_t)(l*3+2)*C_);
    }

    // ---- output transpose ----
    {
        dim3 g(C_/32, T_/32, B_); dim3 bl(32, 8);
        transpose_out_kernel<<<g, bl>>>(tgt, out);
    }
}